// round 11
// baseline (speedup 1.0000x reference)
#include <cuda_runtime.h>
#include <cuda_fp16.h>
#include <math.h>
#include <stdint.h>

// ---------------- problem constants ----------------
#define BB   2
#define SS   1024
#define DD   2048
#define HH   16
#define FF   8192
#define DHD  128
#define HALF 64
#define MM   (BB*SS)          // 2048 rows
#define KAUG (2*DHD)          // 256 augmented K dim

#define HS    0.05f
#define BETA  0.3f
#define ALPHA 0.5f
#define CLIPV 10.0f
#define EPSV  1e-6f
#define SCALE 0.08838834764831845f   // 1/sqrt(128)
#define SQLAM 0.31622776601683794f   // sqrt(0.1)

// ---------------- static device scratch ----------------
static __device__ __align__(128) __half g_xn  [MM*DD];          // rmsnorm/mix out (GEMM A)
static __device__ __align__(128) __half g_tmp [MM*3*DD];        // QKV GEMM out (fp16)
static __device__ __align__(128) float  g_cur [MM*DD];          // pass-1 residual state (= h1)
static __device__ __align__(128) float  g_x2  [MM*DD];          // pass-2 residual state
static __device__ __align__(128) __half g_qa  [BB*HH*SS*KAUG];
static __device__ __align__(128) __half g_ka  [BB*HH*SS*KAUG];
static __device__ __align__(128) __half g_vt  [BB*HH*DHD*SS];   // per-head [DHD, S]
static __device__ __align__(128) float  g_inv [BB*HH*SS];       // per-row 1/sum
static __device__ __align__(128) __half g_sc  [(long long)BB*HH*SS*SS];  // scores fp16
static __device__ __align__(128) __half g_ph  [(long long)BB*HH*SS*SS];  // unnorm probs fp16
static __device__ __align__(128) __half g_gu  [MM*2*FF];        // FFN gate|up out (fp16)
static __device__ __align__(128) __half g_hh  [MM*FF];          // FFN hidden (GEMM A)
// fp16 weights (stacked)
static __device__ __align__(128) __half g_wqkv[3*DD*DD];
static __device__ __align__(128) __half g_wo  [DD*DD];
static __device__ __align__(128) __half g_wgu [2*FF*DD];
static __device__ __align__(128) __half g_wd  [DD*FF];

// ---------------- helpers ----------------
__device__ __forceinline__ uint32_t smem_u32(const void* p) {
    uint32_t a;
    asm("{ .reg .u64 t; cvta.to.shared.u64 t, %1; cvt.u32.u64 %0, t; }" : "=r"(a) : "l"(p));
    return a;
}
__device__ __forceinline__ void cpasync16(uint32_t dst, const void* src) {
    asm volatile("cp.async.cg.shared.global [%0], [%1], 16;" :: "r"(dst), "l"(src));
}
#define CP_COMMIT()  asm volatile("cp.async.commit_group;" ::: "memory")
#define CP_WAIT1()   asm volatile("cp.async.wait_group 1;" ::: "memory")

__device__ __forceinline__ void ldmx4(uint32_t* r, uint32_t addr) {
    asm volatile("ldmatrix.sync.aligned.m8n8.x4.shared.b16 {%0,%1,%2,%3}, [%4];"
        : "=r"(r[0]), "=r"(r[1]), "=r"(r[2]), "=r"(r[3]) : "r"(addr));
}
__device__ __forceinline__ void mma16816(float* c, const uint32_t* a, uint32_t b0, uint32_t b1) {
    asm volatile("mma.sync.aligned.m16n8k16.row.col.f32.f16.f16.f32 "
        "{%0,%1,%2,%3}, {%4,%5,%6,%7}, {%8,%9}, {%0,%1,%2,%3};"
        : "+f"(c[0]), "+f"(c[1]), "+f"(c[2]), "+f"(c[3])
        : "r"(a[0]), "r"(a[1]), "r"(a[2]), "r"(a[3]), "r"(b0), "r"(b1));
}

// ---------------- fp16 tensor-core GEMM (8 warps, 32x64 tiles, single-barrier mainloop) ----------------
// C[M,N](TO) = A[M,K](f16) * B[N,K](f16)^T  (+= if ADD; ADD only with TO=float)
// CTA tile 128x128, chunk = 64 halves (128B rows), 3 smem slots, prefetch-at-top
// (wait_group 1, ONE __syncthreads per chunk), 2 CTA/SM.
// TRI: blockIdx.x enumerates lower-triangle 128x128 blocks (causal scores).
// PVK: K limited to (blockIdx.y+1)*128 halves (causal PV).
// MIX: fused epilogue — normalize by inv[], hadamard-mix along d, transpose-write
//      fp16 into xn [M,D] (C = xn base, sC must be 0). Used by the PV GEMM.
#define HSTAGE 32768    // A:128 rows + B:128 rows, 128B each
#define HSMEM  (3*HSTAGE)

template<typename TO, bool ADD, bool TRI, bool PVK, bool MIX>
__global__ void __launch_bounds__(256, 2) hgemm(
    const __half* __restrict__ A, const __half* __restrict__ B, TO* __restrict__ C,
    int Kn, int Nn, long long sA, long long sB, long long sC,
    const float* __restrict__ invp)
{
    extern __shared__ __align__(128) char sm[];
    const uint32_t sbase = smem_u32(sm);

    int bi, bj;
    if (TRI) {
        int x = blockIdx.x, i = 0;
        while ((i + 1) * (i + 2) / 2 <= x) i++;
        bi = i; bj = x - i * (i + 1) / 2;
    } else { bi = blockIdx.y; bj = blockIdx.x; }

    A += (long long)blockIdx.z * sA + (long long)(bi * 128) * Kn;
    B += (long long)blockIdx.z * sB + (long long)(bj * 128) * Kn;
    C += (long long)blockIdx.z * sC;

    const int NC = PVK ? 2 * (blockIdx.y + 1) : (Kn >> 6);

    const int tid = threadIdx.x, warp = tid >> 5, lane = tid & 31;
    const int gid = lane >> 2, tig = lane & 3;
    const int wm = (warp & 3) * 32, wn = (warp >> 2) * 64;

    const int mi = lane >> 3, ri = lane & 7;
    const int fro = (mi & 1) * 8 + ri;
    const int khalf = mi >> 1;

    float acc[2][8][4];
#pragma unroll
    for (int mt = 0; mt < 2; mt++)
#pragma unroll
        for (int nt = 0; nt < 8; nt++)
#pragma unroll
            for (int j = 0; j < 4; j++) acc[mt][nt][j] = 0.f;

    const int lr = tid >> 3;
    const int lseg = tid & 7;

    // slot = chunk % 3; empty-commit padding past NC keeps wait_group counts uniform
    auto load = [&](int chunk) {
        if (chunk < NC) {
            const uint32_t st = sbase + (uint32_t)(chunk % 3) * HSTAGE;
            const __half* Ag = A + chunk * 64;
            const __half* Bg = B + chunk * 64;
#pragma unroll
            for (int it = 0; it < 4; it++) {
                int r = lr + it * 32;
                uint32_t off = (uint32_t)(r * 128 + ((lseg ^ (r & 7)) << 4));
                cpasync16(st + off,         Ag + (long long)r * Kn + lseg * 8);
                cpasync16(st + 16384 + off, Bg + (long long)r * Kn + lseg * 8);
            }
        }
        CP_COMMIT();
    };

    load(0);
    load(1);

    const int arow[2] = { wm + fro, wm + 16 + fro };
    const int brow[4] = { wn + fro, wn + 16 + fro, wn + 32 + fro, wn + 48 + fro };

    for (int c = 0; c < NC; c++) {
        CP_WAIT1();                       // chunk c's group complete (1 may stay in flight)
        __syncthreads();                  // data visible + slot (c-1)%3 free to overwrite
        load(c + 2);                      // prefetch into slot (c+2)%3 == (c-1)%3

        const uint32_t st = sbase + (uint32_t)(c % 3) * HSTAGE;
#pragma unroll
        for (int kb = 0; kb < 64; kb += 16) {
            const int ks = (kb >> 3) + khalf;
            uint32_t a[2][4], b[4][4];
#pragma unroll
            for (int mt = 0; mt < 2; mt++) {
                int r = arow[mt];
                ldmx4(a[mt], st + (uint32_t)(r * 128 + ((ks ^ (r & 7)) << 4)));
            }
#pragma unroll
            for (int np = 0; np < 4; np++) {
                int r = brow[np];
                ldmx4(b[np], st + 16384u + (uint32_t)(r * 128 + ((ks ^ (r & 7)) << 4)));
            }
#pragma unroll
            for (int mt = 0; mt < 2; mt++)
#pragma unroll
                for (int nt = 0; nt < 8; nt++)
                    mma16816(acc[mt][nt], a[mt], b[nt >> 1][nt & 1], b[nt >> 1][2 + (nt & 1)]);
        }
    }

    if constexpr (MIX) {
        // fused: stage acc to smem, normalize + hadamard mix + transpose -> fp16 xn
        float* stg = (float*)sm;          // 128 x 129 floats = 66048 B (fits in 96KB)
        __syncthreads();                  // all warps done with mainloop smem
#pragma unroll
        for (int mt = 0; mt < 2; mt++) {
            int rr = wm + mt * 16 + gid;
#pragma unroll
            for (int nt = 0; nt < 8; nt++) {
                int cc = wn + nt * 8 + 2 * tig;
                stg[rr * 129 + cc]           = acc[mt][nt][0];
                stg[rr * 129 + cc + 1]       = acc[mt][nt][1];
                stg[(rr + 8) * 129 + cc]     = acc[mt][nt][2];
                stg[(rr + 8) * 129 + cc + 1] = acc[mt][nt][3];
            }
        }
        __syncthreads();
        const int bh = blockIdx.z;
        const int b = bh >> 4, h = bh & 15;
        __half* xo = (__half*)C;          // C = xn base (sC == 0)
        for (int i = tid; i < 128 * 128; i += 256) {
            int r = i >> 7, d = i & 127;
            int sg = bi * 128 + r;
            float iv = invp[(long long)bh * SS + sg];
            float v  = stg[r * 129 + d] * iv;
            float pv = stg[r * 129 + ((d + 127) & 127)] * iv;
            xo[((long long)(b * SS + sg)) * DD + h * DHD + d] =
                __float2half(v * (1.f + HS * pv));
        }
        return;
    }

    // standard epilogue
#pragma unroll
    for (int mt = 0; mt < 2; mt++) {
        int r0 = bi * 128 + wm + mt * 16 + gid;
#pragma unroll
        for (int nt = 0; nt < 8; nt++) {
            int cc = bj * 128 + wn + nt * 8 + 2 * tig;
            TO* p0 = C + (long long)r0 * Nn + cc;
            TO* p1 = p0 + 8 * (long long)Nn;
            if constexpr (sizeof(TO) == 2) {
                *(__half2*)p0 = __floats2half2_rn(acc[mt][nt][0], acc[mt][nt][1]);
                *(__half2*)p1 = __floats2half2_rn(acc[mt][nt][2], acc[mt][nt][3]);
            } else if (ADD) {
                p0[0] += acc[mt][nt][0]; p0[1] += acc[mt][nt][1];
                p1[0] += acc[mt][nt][2]; p1[1] += acc[mt][nt][3];
            } else {
                p0[0] = acc[mt][nt][0]; p0[1] = acc[mt][nt][1];
                p1[0] = acc[mt][nt][2]; p1[1] = acc[mt][nt][3];
            }
        }
    }
}

// ---------------- RMSNorm -> fp16 ----------------
__global__ void rmsnorm_k(const float* __restrict__ x, const float* __restrict__ sc,
                          __half* __restrict__ o)
{
    const int row = blockIdx.x;
    const float* xr = x + (long long)row * DD;
    __half*      orw = o + (long long)row * DD;
    float s = 0.f;
    for (int j = threadIdx.x; j < DD; j += 256) { float v = xr[j]; s += v * v; }
    __shared__ float red[256];
    red[threadIdx.x] = s; __syncthreads();
    for (int t = 128; t > 0; t >>= 1) {
        if (threadIdx.x < t) red[threadIdx.x] += red[threadIdx.x + t];
        __syncthreads();
    }
    float r = rsqrtf(red[0] * (1.0f / DD) + EPSV);
    for (int j = threadIdx.x; j < DD; j += 256) orw[j] = __float2half(xr[j] * r * sc[j]);
}

// ---------------- RoPE + augment (Q and K together) from tmp[M,3D] fp16 ----------------
__global__ void rope_aug2_k(const __half* __restrict__ t,
                            __half* __restrict__ qa, __half* __restrict__ ka)
{
    int idx = blockIdx.x * 256 + threadIdx.x;     // B*S*H*HALF threads
    int d = idx & 63;
    int h = (idx >> 6) & 15;
    int s = (idx >> 10) & 1023;
    int b = idx >> 20;
    const __half* row = t + ((long long)b * SS + s) * (3 * DD);
    float q1 = __half2float(row[h * DHD + d]);
    float q2 = __half2float(row[h * DHD + HALF + d]);
    float k1 = __half2float(row[DD + h * DHD + d]);
    float k2 = __half2float(row[DD + h * DHD + HALF + d]);
    float inv = __expf(-(float)d * (9.210340371976184f / 64.0f));
    float ang = (float)s * inv;
    float cs, sn; __sincosf(ang, &sn, &cs);
    long long base = (((long long)(b * HH + h)) * SS + s) * KAUG;
    float qo1 = q1 * cs - q2 * sn, qo2 = q1 * sn + q2 * cs;
    float ko1 = k1 * cs - k2 * sn, ko2 = k1 * sn + k2 * cs;
    qa[base + d]              = __float2half(qo1);
    qa[base + HALF + d]       = __float2half(qo2);
    qa[base + DHD + d]        = __float2half(SQLAM * qo1 * qo1);
    qa[base + DHD + HALF + d] = __float2half(SQLAM * qo2 * qo2);
    ka[base + d]              = __float2half(ko1);
    ka[base + HALF + d]       = __float2half(ko2);
    ka[base + DHD + d]        = __float2half(SQLAM * ko1 * ko1);
    ka[base + DHD + HALF + d] = __float2half(SQLAM * ko2 * ko2);
}

// ---------------- V transpose from tmp[M,3D] fp16 -> per-head [DHD,S] ----------------
__global__ void vt_k(const __half* __restrict__ t, __half* __restrict__ out)
{
    __shared__ __half tl[32][33];
    int bh = blockIdx.z;
    int b = bh >> 4, h = bh & 15;
    int s0 = blockIdx.x * 32, d0 = blockIdx.y * 32;
    int tx = threadIdx.x & 31, ty = threadIdx.x >> 5;
    for (int i = ty; i < 32; i += 8) {
        int s = s0 + i, d = d0 + tx;
        tl[i][tx] = t[((long long)(b * SS + s)) * (3 * DD) + 2 * DD + h * DHD + d];
    }
    __syncthreads();
    for (int i = ty; i < 32; i += 8) {
        int d = d0 + i, s = s0 + tx;
        out[((long long)bh * DHD + d) * SS + s] = tl[tx][i];
    }
}

// ---------------- causal softmax: fp16 scores in, single exp, unnormalized out ----------------
__global__ void softmax_k(const __half* __restrict__ sc, __half* __restrict__ ph,
                          float* __restrict__ inv)
{
    long long row = blockIdx.x;
    int i = (int)(row % SS);
    int lim = i | 127;                    // zero-fill out to PV block boundary
    const __half* p = sc + row * SS;
    __half* q = ph + row * SS;
    int tid = threadIdx.x;
    __shared__ float red[256];

    float v[4];
    float m = -1e30f;
#pragma unroll
    for (int k = 0; k < 4; k++) {
        int j = tid + 256 * k;
        v[k] = (j <= i) ? __half2float(p[j]) * SCALE : -1e30f;
        m = fmaxf(m, v[k]);
    }
    red[tid] = m; __syncthreads();
    for (int t = 128; t > 0; t >>= 1) {
        if (tid < t) red[tid] = fmaxf(red[tid], red[tid + t]);
        __syncthreads();
    }
    m = red[0]; __syncthreads();

    float sum = 0.f;
#pragma unroll
    for (int k = 0; k < 4; k++) {
        int j = tid + 256 * k;
        if (j <= i) {
            float e = __expf(v[k] - m);
            q[j] = __float2half(e);
            sum += e;
        } else if (j <= lim) {
            q[j] = __half(0.f);
        }
    }
    red[tid] = sum; __syncthreads();
    for (int t = 128; t > 0; t >>= 1) {
        if (tid < t) red[tid] += red[tid + t];
        __syncthreads();
    }
    if (tid == 0) inv[row] = 1.f / red[0];
}

// ---------------- fused silu*up + hadamard mix, chunked (9 exps / 8 outputs) ----------------
__global__ void silu_mix_k(const __half* __restrict__ gu, __half* __restrict__ hh)
{
    int t = blockIdx.x * 256 + threadIdx.x;       // M*F/8 threads
    int m = t >> 10;                               // F/8 = 1024 chunks per row
    int c0 = (t & 1023) << 3;
    const __half* grow = gu + (long long)m * (2 * FF);
    const __half* urow = grow + FF;
    int pc = (c0 + FF - 1) & (FF - 1);
    float gp = __half2float(grow[pc]);
    float up = __half2float(urow[pc]);
    float hprev = gp / (1.f + __expf(-gp)) * up;
    __half* orow = hh + (long long)m * FF + c0;
#pragma unroll
    for (int k = 0; k < 8; k++) {
        float g = __half2float(grow[c0 + k]);
        float u = __half2float(urow[c0 + k]);
        float h = g / (1.f + __expf(-g)) * u;
        orow[k] = __float2half(h * (1.f + HS * hprev));
        hprev = h;
    }
}

// ---------------- misc elementwise ----------------
__global__ void copy_k(float* __restrict__ dst, const float* __restrict__ src, int n)
{ int i = blockIdx.x * 256 + threadIdx.x; if (i < n) dst[i] = src[i]; }

// vectorized fp32->fp16 (n divisible by 4)
__global__ void w2h_k(__half* __restrict__ dst, const float* __restrict__ src, int n4)
{
    int i = blockIdx.x * 256 + threadIdx.x;
    if (i < n4) {
        float4 v = ((const float4*)src)[i];
        __half2 lo = __floats2half2_rn(v.x, v.y);
        __half2 hi = __floats2half2_rn(v.z, v.w);
        ((uint2*)dst)[i] = make_uint2(*(uint32_t*)&lo, *(uint32_t*)&hi);
    }
}

__global__ void x2_k(float* __restrict__ dst, const float* __restrict__ h1,
                     const float* __restrict__ x, int n)
{ int i = blockIdx.x * 256 + threadIdx.x; if (i < n) dst[i] = (1.f + BETA) * h1[i] - BETA * x[i]; }

__global__ void final_k(float* __restrict__ out, const float* __restrict__ h1,
                        const float* __restrict__ h2, int n)
{
    int i = blockIdx.x * 256 + threadIdx.x;
    if (i < n) {
        float v = ALPHA * h1[i] + (1.f - ALPHA) * h2[i];
        out[i] = fminf(fmaxf(v, -CLIPV), CLIPV);
    }
}

// ---------------- host orchestration ----------------
static void run_pass(const __half* wqkv, const __half* wo, const __half* wgu, const __half* wd,
                     const float* na, const float* nb,
                     float* cur, __half* xn, __half* tmp,
                     __half* qa, __half* ka, __half* vt, float* inv,
                     __half* sc, __half* ph, __half* gu, __half* hh)
{
    const int nMF = MM * FF;

    rmsnorm_k<<<MM, 256>>>(cur, na, xn);

    // fused QKV: [M, 3D](fp16) = xn * wqkv^T
    hgemm<__half,false,false,false,false><<<dim3(3*DD/128, MM/128, 1), 256, HSMEM>>>(
        xn, wqkv, tmp, DD, 3*DD, 0, 0, 0, nullptr);
    rope_aug2_k<<<(BB*SS*HH*HALF)/256, 256>>>(tmp, qa, ka);
    vt_k<<<dim3(SS/32, DHD/32, BB*HH), 256>>>(tmp, vt);

    // causal scores (fp16 out): lower-triangle blocks only
    hgemm<__half,false,true,false,false><<<dim3(36, 1, BB*HH), 256, HSMEM>>>(
        qa, ka, sc, KAUG, SS,
        (long long)SS*KAUG, (long long)SS*KAUG, (long long)SS*SS, nullptr);
    softmax_k<<<BB*HH*SS, 256>>>(sc, ph, inv);
    // PV with causal K truncation + fused normalize/mix/transpose epilogue -> xn
    hgemm<__half,false,false,true,true><<<dim3(1, SS/128, BB*HH), 256, HSMEM>>>(
        ph, vt, xn, SS, DHD,
        (long long)SS*SS, (long long)SS*DHD, 0, inv);

    hgemm<float,true,false,false,false><<<dim3(DD/128, MM/128, 1), 256, HSMEM>>>(
        xn, wo, cur, DD, DD, 0, 0, 0, nullptr);

    rmsnorm_k<<<MM, 256>>>(cur, nb, xn);
    // fused gate|up: [M, 2F](fp16)
    hgemm<__half,false,false,false,false><<<dim3(2*FF/128, MM/128, 1), 256, HSMEM>>>(
        xn, wgu, gu, DD, 2*FF, 0, 0, 0, nullptr);
    silu_mix_k<<<nMF/8/256, 256>>>(gu, hh);
    hgemm<float,true,false,false,false><<<dim3(DD/128, MM/128, 1), 256, HSMEM>>>(
        hh, wd, cur, FF, DD, 0, 0, 0, nullptr);
}

extern "C" void kernel_launch(void* const* d_in, const int* in_sizes, int n_in,
                              void* d_out, int out_size)
{
    (void)in_sizes; (void)n_in; (void)out_size;
    const float* x   = (const float*)d_in[0];
    const float* Wq0 = (const float*)d_in[1];
    const float* Wk0 = (const float*)d_in[2];
    const float* Wv0 = (const float*)d_in[3];
    const float* Wo0 = (const float*)d_in[4];
    // d_in[5] = gate_w: unused (rotate_half invariance => o2 == o1)
    const float* n1 = (const float*)d_in[6];
    const float* n2 = (const float*)d_in[7];
    const float* n3 = (const float*)d_in[8];
    const float* n4 = (const float*)d_in[9];
    const float* Wg0 = (const float*)d_in[10];
    const float* Wu0 = (const float*)d_in[11];
    const float* Wd0 = (const float*)d_in[12];
    float* out = (float*)d_out;

    cudaFuncSetAttribute(hgemm<__half,false,false,false,false>, cudaFuncAttributeMaxDynamicSharedMemorySize, HSMEM);
    cudaFuncSetAttribute(hgemm<float,true,false,false,false>,   cudaFuncAttributeMaxDynamicSharedMemorySize, HSMEM);
    cudaFuncSetAttribute(hgemm<__half,false,true,false,false>,  cudaFuncAttributeMaxDynamicSharedMemorySize, HSMEM);
    cudaFuncSetAttribute(hgemm<__half,false,false,true,true>,   cudaFuncAttributeMaxDynamicSharedMemorySize, HSMEM);

    __half *xn, *tmp, *qa, *ka, *vt, *sc, *ph, *gu, *hh, *wqkv, *wo, *wgu, *wd;
    float *cur, *x2, *inv;
    cudaGetSymbolAddress((void**)&xn,  g_xn);
    cudaGetSymbolAddress((void**)&tmp, g_tmp);
    cudaGetSymbolAddress((void**)&cur, g_cur);
    cudaGetSymbolAddress((void**)&x2,  g_x2);
    cudaGetSymbolAddress((void**)&qa,  g_qa);
    cudaGetSymbolAddress((void**)&ka,  g_ka);
    cudaGetSymbolAddress((void**)&vt,  g_vt);
    cudaGetSymbolAddress((void**)&inv, g_inv);
    cudaGetSymbolAddress((void**)&sc,  g_sc);
    cudaGetSymbolAddress((void**)&ph,  g_ph);
    cudaGetSymbolAddress((void**)&gu,  g_gu);
    cudaGetSymbolAddress((void**)&hh,  g_hh);
    cudaGetSymbolAddress((void**)&wqkv,g_wqkv);
    cudaGetSymbolAddress((void**)&wo,  g_wo);
    cudaGetSymbolAddress((void**)&wgu, g_wgu);
    cudaGetSymbolAddress((void**)&wd,  g_wd);

    const int nMD = MM * DD;

    // weights -> fp16 (stacked, vectorized)
    w2h_k<<<(DD*DD/4+255)/256, 256>>>(wqkv,            Wq0, DD*DD/4);
    w2h_k<<<(DD*DD/4+255)/256, 256>>>(wqkv + DD*DD,    Wk0, DD*DD/4);
    w2h_k<<<(DD*DD/4+255)/256, 256>>>(wqkv + 2*DD*DD,  Wv0, DD*DD/4);
    w2h_k<<<(DD*DD/4+255)/256, 256>>>(wo,              Wo0, DD*DD/4);
    w2h_k<<<(FF*DD/4+255)/256, 256>>>(wgu,             Wg0, FF*DD/4);
    w2h_k<<<(FF*DD/4+255)/256, 256>>>(wgu + FF*DD,     Wu0, FF*DD/4);
    w2h_k<<<(FF*DD/4+255)/256, 256>>>(wd,              Wd0, FF*DD/4);

    // pass 1 (accumulates into cur; cur becomes h1 — no copy needed)
    copy_k<<<(nMD+255)/256, 256>>>(cur, x, nMD);
    run_pass(wqkv, wo, wgu, wd, n1, n2, cur, xn, tmp, qa, ka, vt, inv, sc, ph, gu, hh);

    // x2 = h1 + beta*(h1 - x)  -> separate buffer, preserving cur (= h1)
    x2_k<<<(nMD+255)/256, 256>>>(x2, cur, x, nMD);

    // pass 2 (accumulates into x2)
    run_pass(wqkv, wo, wgu, wd, n3, n4, x2, xn, tmp, qa, ka, vt, inv, sc, ph, gu, hh);

    // out = clip(alpha*h1 + (1-alpha)*h2)
    final_k<<<(nMD+255)/256, 256>>>(out, cur, x2, nMD);
}

// round 12
// speedup vs baseline: 1.0146x; 1.0146x over previous
#include <cuda_runtime.h>
#include <cuda_fp16.h>
#include <math.h>
#include <stdint.h>

// ---------------- problem constants ----------------
#define BB   2
#define SS   1024
#define DD   2048
#define HH   16
#define FF   8192
#define DHD  128
#define HALF 64
#define MM   (BB*SS)          // 2048 rows
#define KAUG (2*DHD)          // 256 augmented K dim

#define HS    0.05f
#define BETA  0.3f
#define ALPHA 0.5f
#define CLIPV 10.0f
#define EPSV  1e-6f
#define SCALE 0.08838834764831845f   // 1/sqrt(128)
#define SQLAM 0.31622776601683794f   // sqrt(0.1)

// ---------------- static device scratch ----------------
static __device__ __align__(128) __half g_xn  [MM*DD];          // rmsnorm/mix out (GEMM A)
static __device__ __align__(128) float  g_cur [MM*DD];          // pass-1 residual state (= h1)
static __device__ __align__(128) float  g_x2  [MM*DD];          // pass-2 residual state
static __device__ __align__(128) __half g_qa  [BB*HH*SS*KAUG];
static __device__ __align__(128) __half g_ka  [BB*HH*SS*KAUG];
static __device__ __align__(128) __half g_vt  [BB*HH*DHD*SS];   // per-head [DHD, S]
static __device__ __align__(128) float  g_inv [BB*HH*SS];       // per-row 1/sum
static __device__ __align__(128) __half g_sc  [(long long)BB*HH*SS*SS];  // scores fp16
static __device__ __align__(128) __half g_ph  [(long long)BB*HH*SS*SS];  // unnorm probs fp16
static __device__ __align__(128) __half g_hr  [MM*FF];          // FFN silu(g)*u (unmixed)
static __device__ __align__(128) __half g_hh  [MM*FF];          // FFN hidden mixed (GEMM A)
// fp16 weights
static __device__ __align__(128) __half g_wqkv[3*DD*DD];
static __device__ __align__(128) __half g_wo  [DD*DD];
static __device__ __align__(128) __half g_wgu [2*FF*DD];        // interleaved (gate_j, up_j) rows
static __device__ __align__(128) __half g_wd  [DD*FF];

// ---------------- helpers ----------------
__device__ __forceinline__ uint32_t smem_u32(const void* p) {
    uint32_t a;
    asm("{ .reg .u64 t; cvta.to.shared.u64 t, %1; cvt.u32.u64 %0, t; }" : "=r"(a) : "l"(p));
    return a;
}
__device__ __forceinline__ void cpasync16(uint32_t dst, const void* src) {
    asm volatile("cp.async.cg.shared.global [%0], [%1], 16;" :: "r"(dst), "l"(src));
}
#define CP_COMMIT()  asm volatile("cp.async.commit_group;" ::: "memory")
#define CP_WAIT1()   asm volatile("cp.async.wait_group 1;" ::: "memory")

__device__ __forceinline__ void ldmx4(uint32_t* r, uint32_t addr) {
    asm volatile("ldmatrix.sync.aligned.m8n8.x4.shared.b16 {%0,%1,%2,%3}, [%4];"
        : "=r"(r[0]), "=r"(r[1]), "=r"(r[2]), "=r"(r[3]) : "r"(addr));
}
__device__ __forceinline__ void mma16816(float* c, const uint32_t* a, uint32_t b0, uint32_t b1) {
    asm volatile("mma.sync.aligned.m16n8k16.row.col.f32.f16.f16.f32 "
        "{%0,%1,%2,%3}, {%4,%5,%6,%7}, {%8,%9}, {%0,%1,%2,%3};"
        : "+f"(c[0]), "+f"(c[1]), "+f"(c[2]), "+f"(c[3])
        : "r"(a[0]), "r"(a[1]), "r"(a[2]), "r"(a[3]), "r"(b0), "r"(b1));
}

// ---------------- fp16 tensor-core GEMM with fused epilogues ----------------
// C[M,N](TO) = A[M,K](f16) * B[N,K](f16)^T  (+= if ADD; ADD only with TO=float)
// CTA tile 128x128, chunk = 64 halves (128B rows), 3 smem slots, single-barrier
// mainloop (wait_group 1 + prefetch at top), 2 CTA/SM.
// TRI: blockIdx.x enumerates lower-triangle 128x128 blocks (causal scores).
// PVK: K limited to (blockIdx.y+1)*128 halves (causal PV).
// MIX: PV epilogue — normalize by inv[], hadamard-mix along d, transpose-write fp16 xn.
// QKV: epilogue applies RoPE+augment for q/k head tiles (writes C=qa / aux1=ka)
//      and transposes v head tiles into aux2=vt. bj in [0,48): 16 q, 16 k, 16 v heads.
// GLU: wgu rows interleaved (gate,up); epilogue computes silu(g)*u from register
//      pairs and writes fp16 [M,F] (C base, stride FF).
#define HSTAGE 32768    // A:128 rows + B:128 rows, 128B each
#define HSMEM  (3*HSTAGE)

template<typename TO, bool ADD, bool TRI, bool PVK, bool MIX, bool QKV, bool GLU>
__global__ void __launch_bounds__(256, 2) hgemm(
    const __half* __restrict__ A, const __half* __restrict__ B, TO* __restrict__ C,
    int Kn, int Nn, long long sA, long long sB, long long sC,
    const float* __restrict__ invp, __half* __restrict__ aux1, __half* __restrict__ aux2)
{
    extern __shared__ __align__(128) char sm[];
    const uint32_t sbase = smem_u32(sm);

    int bi, bj;
    if (TRI) {
        int x = blockIdx.x, i = 0;
        while ((i + 1) * (i + 2) / 2 <= x) i++;
        bi = i; bj = x - i * (i + 1) / 2;
    } else { bi = blockIdx.y; bj = blockIdx.x; }

    A += (long long)blockIdx.z * sA + (long long)(bi * 128) * Kn;
    B += (long long)blockIdx.z * sB + (long long)(bj * 128) * Kn;
    C += (long long)blockIdx.z * sC;

    const int NC = PVK ? 2 * (blockIdx.y + 1) : (Kn >> 6);

    const int tid = threadIdx.x, warp = tid >> 5, lane = tid & 31;
    const int gid = lane >> 2, tig = lane & 3;
    const int wm = (warp & 3) * 32, wn = (warp >> 2) * 64;

    const int mi = lane >> 3, ri = lane & 7;
    const int fro = (mi & 1) * 8 + ri;
    const int khalf = mi >> 1;

    float acc[2][8][4];
#pragma unroll
    for (int mt = 0; mt < 2; mt++)
#pragma unroll
        for (int nt = 0; nt < 8; nt++)
#pragma unroll
            for (int j = 0; j < 4; j++) acc[mt][nt][j] = 0.f;

    const int lr = tid >> 3;
    const int lseg = tid & 7;

    auto load = [&](int chunk) {
        if (chunk < NC) {
            const uint32_t st = sbase + (uint32_t)(chunk % 3) * HSTAGE;
            const __half* Ag = A + chunk * 64;
            const __half* Bg = B + chunk * 64;
#pragma unroll
            for (int it = 0; it < 4; it++) {
                int r = lr + it * 32;
                uint32_t off = (uint32_t)(r * 128 + ((lseg ^ (r & 7)) << 4));
                cpasync16(st + off,         Ag + (long long)r * Kn + lseg * 8);
                cpasync16(st + 16384 + off, Bg + (long long)r * Kn + lseg * 8);
            }
        }
        CP_COMMIT();
    };

    load(0);
    load(1);

    const int arow[2] = { wm + fro, wm + 16 + fro };
    const int brow[4] = { wn + fro, wn + 16 + fro, wn + 32 + fro, wn + 48 + fro };

    for (int c = 0; c < NC; c++) {
        CP_WAIT1();
        __syncthreads();
        load(c + 2);

        const uint32_t st = sbase + (uint32_t)(c % 3) * HSTAGE;
#pragma unroll
        for (int kb = 0; kb < 64; kb += 16) {
            const int ks = (kb >> 3) + khalf;
            uint32_t a[2][4], b[4][4];
#pragma unroll
            for (int mt = 0; mt < 2; mt++) {
                int r = arow[mt];
                ldmx4(a[mt], st + (uint32_t)(r * 128 + ((ks ^ (r & 7)) << 4)));
            }
#pragma unroll
            for (int np = 0; np < 4; np++) {
                int r = brow[np];
                ldmx4(b[np], st + 16384u + (uint32_t)(r * 128 + ((ks ^ (r & 7)) << 4)));
            }
#pragma unroll
            for (int mt = 0; mt < 2; mt++)
#pragma unroll
                for (int nt = 0; nt < 8; nt++)
                    mma16816(acc[mt][nt], a[mt], b[nt >> 1][nt & 1], b[nt >> 1][2 + (nt & 1)]);
        }
    }

    if constexpr (GLU) {
        // register pairs (acc[0],acc[1]) / (acc[2],acc[3]) = (gate, up) for one hidden col
        __half* hr = (__half*)C;          // stride FF
#pragma unroll
        for (int mt = 0; mt < 2; mt++) {
            int row0 = bi * 128 + wm + mt * 16 + gid;
#pragma unroll
            for (int nt = 0; nt < 8; nt++) {
                int jg = bj * 64 + ((wn + nt * 8) >> 1) + tig;
                float g0 = acc[mt][nt][0], u0 = acc[mt][nt][1];
                float g1 = acc[mt][nt][2], u1 = acc[mt][nt][3];
                hr[(long long)row0 * FF + jg]       = __float2half(g0 / (1.f + __expf(-g0)) * u0);
                hr[(long long)(row0 + 8) * FF + jg] = __float2half(g1 / (1.f + __expf(-g1)) * u1);
            }
        }
        return;
    }

    if constexpr (MIX || QKV) {
        // stage fp32 accumulators to smem (128 x 129)
        float* stg = (float*)sm;
        __syncthreads();
#pragma unroll
        for (int mt = 0; mt < 2; mt++) {
            int rr = wm + mt * 16 + gid;
#pragma unroll
            for (int nt = 0; nt < 8; nt++) {
                int cc = wn + nt * 8 + 2 * tig;
                stg[rr * 129 + cc]           = acc[mt][nt][0];
                stg[rr * 129 + cc + 1]       = acc[mt][nt][1];
                stg[(rr + 8) * 129 + cc]     = acc[mt][nt][2];
                stg[(rr + 8) * 129 + cc + 1] = acc[mt][nt][3];
            }
        }
        __syncthreads();
    }

    if constexpr (MIX) {
        float* stg = (float*)sm;
        const int bh = blockIdx.z;
        const int b = bh >> 4, h = bh & 15;
        __half* xo = (__half*)C;          // C = xn base (sC == 0)
        for (int i = tid; i < 128 * 128; i += 256) {
            int r = i >> 7, d = i & 127;
            int sg = bi * 128 + r;
            float iv = invp[(long long)bh * SS + sg];
            float v  = stg[r * 129 + d] * iv;
            float pv = stg[r * 129 + ((d + 127) & 127)] * iv;
            xo[((long long)(b * SS + sg)) * DD + h * DHD + d] =
                __float2half(v * (1.f + HS * pv));
        }
        return;
    }

    if constexpr (QKV) {
        float* stg = (float*)sm;
        const int htype = bj >> 4, h = bj & 15;
        const int bq = (bi * 128) >> 10;     // batch index (128 | 1024)
        const int s0 = (bi * 128) & 1023;
        if (htype < 2) {
            __half* dst = (htype == 0) ? (__half*)C : aux1;   // qa : ka
            for (int i = tid; i < 128 * 64; i += 256) {
                int r = i >> 6, dd = i & 63;
                int s = s0 + r;
                float v1 = stg[r * 129 + dd];
                float v2 = stg[r * 129 + dd + 64];
                float invf = __expf(-(float)dd * (9.210340371976184f / 64.0f));
                float ang = (float)s * invf;
                float cs, sn; __sincosf(ang, &sn, &cs);
                float o1 = v1 * cs - v2 * sn;
                float o2 = v1 * sn + v2 * cs;
                long long base = (((long long)(bq * HH + h)) * SS + s) * KAUG;
                dst[base + dd]              = __float2half(o1);
                dst[base + HALF + dd]       = __float2half(o2);
                dst[base + DHD + dd]        = __float2half(SQLAM * o1 * o1);
                dst[base + DHD + HALF + dd] = __float2half(SQLAM * o2 * o2);
            }
        } else {
            const int bh = bq * HH + h;
            for (int i = tid; i < 128 * 128; i += 256) {
                int d = i >> 7, sl = i & 127;
                aux2[((long long)(bh * DHD + d)) * SS + s0 + sl] =
                    __float2half(stg[sl * 129 + d]);
            }
        }
        return;
    }

    // standard epilogue
#pragma unroll
    for (int mt = 0; mt < 2; mt++) {
        int r0 = bi * 128 + wm + mt * 16 + gid;
#pragma unroll
        for (int nt = 0; nt < 8; nt++) {
            int cc = bj * 128 + wn + nt * 8 + 2 * tig;
            TO* p0 = C + (long long)r0 * Nn + cc;
            TO* p1 = p0 + 8 * (long long)Nn;
            if constexpr (sizeof(TO) == 2) {
                *(__half2*)p0 = __floats2half2_rn(acc[mt][nt][0], acc[mt][nt][1]);
                *(__half2*)p1 = __floats2half2_rn(acc[mt][nt][2], acc[mt][nt][3]);
            } else if (ADD) {
                p0[0] += acc[mt][nt][0]; p0[1] += acc[mt][nt][1];
                p1[0] += acc[mt][nt][2]; p1[1] += acc[mt][nt][3];
            } else {
                p0[0] = acc[mt][nt][0]; p0[1] = acc[mt][nt][1];
                p1[0] = acc[mt][nt][2]; p1[1] = acc[mt][nt][3];
            }
        }
    }
}

// ---------------- RMSNorm -> fp16 ----------------
__global__ void rmsnorm_k(const float* __restrict__ x, const float* __restrict__ sc,
                          __half* __restrict__ o)
{
    const int row = blockIdx.x;
    const float* xr = x + (long long)row * DD;
    __half*      orw = o + (long long)row * DD;
    float s = 0.f;
    for (int j = threadIdx.x; j < DD; j += 256) { float v = xr[j]; s += v * v; }
    __shared__ float red[256];
    red[threadIdx.x] = s; __syncthreads();
    for (int t = 128; t > 0; t >>= 1) {
        if (threadIdx.x < t) red[threadIdx.x] += red[threadIdx.x + t];
        __syncthreads();
    }
    float r = rsqrtf(red[0] * (1.0f / DD) + EPSV);
    for (int j = threadIdx.x; j < DD; j += 256) orw[j] = __float2half(xr[j] * r * sc[j]);
}

// ---------------- causal softmax: fp16 scores in, single exp, unnormalized out ----------------
__global__ void softmax_k(const __half* __restrict__ sc, __half* __restrict__ ph,
                          float* __restrict__ inv)
{
    long long row = blockIdx.x;
    int i = (int)(row % SS);
    int lim = i | 127;
    const __half* p = sc + row * SS;
    __half* q = ph + row * SS;
    int tid = threadIdx.x;
    __shared__ float red[256];

    float v[4];
    float m = -1e30f;
#pragma unroll
    for (int k = 0; k < 4; k++) {
        int j = tid + 256 * k;
        v[k] = (j <= i) ? __half2float(p[j]) * SCALE : -1e30f;
        m = fmaxf(m, v[k]);
    }
    red[tid] = m; __syncthreads();
    for (int t = 128; t > 0; t >>= 1) {
        if (tid < t) red[tid] = fmaxf(red[tid], red[tid + t]);
        __syncthreads();
    }
    m = red[0]; __syncthreads();

    float sum = 0.f;
#pragma unroll
    for (int k = 0; k < 4; k++) {
        int j = tid + 256 * k;
        if (j <= i) {
            float e = __expf(v[k] - m);
            q[j] = __float2half(e);
            sum += e;
        } else if (j <= lim) {
            q[j] = __half(0.f);
        }
    }
    red[tid] = sum; __syncthreads();
    for (int t = 128; t > 0; t >>= 1) {
        if (tid < t) red[tid] += red[tid + t];
        __syncthreads();
    }
    if (tid == 0) inv[row] = 1.f / red[0];
}

// ---------------- FFN hadamard mix (no exp): hh[c] = hr[c]*(1+HS*hr[c-1]) ----------------
__global__ void mixf_k(const __half* __restrict__ hr, __half* __restrict__ hh)
{
    int t = blockIdx.x * 256 + threadIdx.x;       // M*F/8 threads
    int m = t >> 10;
    int c0 = (t & 1023) << 3;
    const __half* row = hr + (long long)m * FF;
    float hprev = __half2float(row[(c0 + FF - 1) & (FF - 1)]);
    __half* orow = hh + (long long)m * FF + c0;
#pragma unroll
    for (int k = 0; k < 8; k++) {
        float h = __half2float(row[c0 + k]);
        orow[k] = __float2half(h * (1.f + HS * hprev));
        hprev = h;
    }
}

// ---------------- misc elementwise ----------------
__global__ void copy_k(float* __restrict__ dst, const float* __restrict__ src, int n)
{ int i = blockIdx.x * 256 + threadIdx.x; if (i < n) dst[i] = src[i]; }

// fp32 -> fp16, 4x float4 per thread (n16 = n/16)
__global__ void w2h_k(__half* __restrict__ dst, const float* __restrict__ src, int n16)
{
    int i = blockIdx.x * 256 + threadIdx.x;
    if (i < n16) {
#pragma unroll
        for (int k = 0; k < 4; k++) {
            float4 v = ((const float4*)src)[i * 4 + k];
            __half2 lo = __floats2half2_rn(v.x, v.y);
            __half2 hi = __floats2half2_rn(v.z, v.w);
            ((uint2*)dst)[i * 4 + k] = make_uint2(*(uint32_t*)&lo, *(uint32_t*)&hi);
        }
    }
}

// gate/up interleave conversion: dst row 2j <- Wg row j, row 2j+1 <- Wu row j
__global__ void w2h_glu_k(__half* __restrict__ dst, const float* __restrict__ wg,
                          const float* __restrict__ wu, int n4)   // n4 = FF*DD/4
{
    int e = blockIdx.x * 256 + threadIdx.x;
    if (e < n4) {
        int j = e >> 9, c = e & 511;                 // DD/4 = 512 float4 per row
        float4 vg = ((const float4*)wg)[e];
        float4 vu = ((const float4*)wu)[e];
        __half2 glo = __floats2half2_rn(vg.x, vg.y), ghi = __floats2half2_rn(vg.z, vg.w);
        __half2 ulo = __floats2half2_rn(vu.x, vu.y), uhi = __floats2half2_rn(vu.z, vu.w);
        ((uint2*)dst)[((long long)(2 * j) << 9) + c]     = make_uint2(*(uint32_t*)&glo, *(uint32_t*)&ghi);
        ((uint2*)dst)[((long long)(2 * j + 1) << 9) + c] = make_uint2(*(uint32_t*)&ulo, *(uint32_t*)&uhi);
    }
}

__global__ void x2_k(float* __restrict__ dst, const float* __restrict__ h1,
                     const float* __restrict__ x, int n)
{ int i = blockIdx.x * 256 + threadIdx.x; if (i < n) dst[i] = (1.f + BETA) * h1[i] - BETA * x[i]; }

__global__ void final_k(float* __restrict__ out, const float* __restrict__ h1,
                        const float* __restrict__ h2, int n)
{
    int i = blockIdx.x * 256 + threadIdx.x;
    if (i < n) {
        float v = ALPHA * h1[i] + (1.f - ALPHA) * h2[i];
        out[i] = fminf(fmaxf(v, -CLIPV), CLIPV);
    }
}

// ---------------- host orchestration ----------------
static void run_pass(const __half* wqkv, const __half* wo, const __half* wgu, const __half* wd,
                     const float* na, const float* nb,
                     float* cur, __half* xn,
                     __half* qa, __half* ka, __half* vt, float* inv,
                     __half* sc, __half* ph, __half* hr, __half* hh)
{
    const int nMF = MM * FF;

    rmsnorm_k<<<MM, 256>>>(cur, na, xn);

    // fused QKV + RoPE/augment + V-transpose: writes qa, ka, vt directly
    hgemm<__half,false,false,false,false,true,false><<<dim3(48, MM/128, 1), 256, HSMEM>>>(
        xn, wqkv, qa, DD, 3*DD, 0, 0, 0, nullptr, ka, vt);

    // causal scores (fp16 out): lower-triangle blocks only
    hgemm<__half,false,true,false,false,false,false><<<dim3(36, 1, BB*HH), 256, HSMEM>>>(
        qa, ka, sc, KAUG, SS,
        (long long)SS*KAUG, (long long)SS*KAUG, (long long)SS*SS, nullptr, nullptr, nullptr);
    softmax_k<<<BB*HH*SS, 256>>>(sc, ph, inv);
    // PV with causal K truncation + fused normalize/mix/transpose epilogue -> xn
    hgemm<__half,false,false,true,true,false,false><<<dim3(1, SS/128, BB*HH), 256, HSMEM>>>(
        ph, vt, xn, SS, DHD,
        (long long)SS*SS, (long long)SS*DHD, 0, inv, nullptr, nullptr);

    hgemm<float,true,false,false,false,false,false><<<dim3(DD/128, MM/128, 1), 256, HSMEM>>>(
        xn, wo, cur, DD, DD, 0, 0, 0, nullptr, nullptr, nullptr);

    rmsnorm_k<<<MM, 256>>>(cur, nb, xn);
    // fused gate|up (interleaved weights) + silu*up epilogue -> hr [M,F]
    hgemm<__half,false,false,false,false,false,true><<<dim3(2*FF/128, MM/128, 1), 256, HSMEM>>>(
        xn, wgu, hr, DD, 2*FF, 0, 0, 0, nullptr, nullptr, nullptr);
    mixf_k<<<nMF/8/256, 256>>>(hr, hh);
    hgemm<float,true,false,false,false,false,false><<<dim3(DD/128, MM/128, 1), 256, HSMEM>>>(
        hh, wd, cur, FF, DD, 0, 0, 0, nullptr, nullptr, nullptr);
}

extern "C" void kernel_launch(void* const* d_in, const int* in_sizes, int n_in,
                              void* d_out, int out_size)
{
    (void)in_sizes; (void)n_in; (void)out_size;
    const float* x   = (const float*)d_in[0];
    const float* Wq0 = (const float*)d_in[1];
    const float* Wk0 = (const float*)d_in[2];
    const float* Wv0 = (const float*)d_in[3];
    const float* Wo0 = (const float*)d_in[4];
    // d_in[5] = gate_w: unused (rotate_half invariance => o2 == o1)
    const float* n1 = (const float*)d_in[6];
    const float* n2 = (const float*)d_in[7];
    const float* n3 = (const float*)d_in[8];
    const float* n4 = (const float*)d_in[9];
    const float* Wg0 = (const float*)d_in[10];
    const float* Wu0 = (const float*)d_in[11];
    const float* Wd0 = (const float*)d_in[12];
    float* out = (float*)d_out;

    cudaFuncSetAttribute(hgemm<__half,false,false,false,false,true,false>, cudaFuncAttributeMaxDynamicSharedMemorySize, HSMEM);
    cudaFuncSetAttribute(hgemm<float,true,false,false,false,false,false>,  cudaFuncAttributeMaxDynamicSharedMemorySize, HSMEM);
    cudaFuncSetAttribute(hgemm<__half,false,true,false,false,false,false>, cudaFuncAttributeMaxDynamicSharedMemorySize, HSMEM);
    cudaFuncSetAttribute(hgemm<__half,false,false,true,true,false,false>,  cudaFuncAttributeMaxDynamicSharedMemorySize, HSMEM);
    cudaFuncSetAttribute(hgemm<__half,false,false,false,false,false,true>, cudaFuncAttributeMaxDynamicSharedMemorySize, HSMEM);

    __half *xn, *qa, *ka, *vt, *sc, *ph, *hr, *hh, *wqkv, *wo, *wgu, *wd;
    float *cur, *x2, *inv;
    cudaGetSymbolAddress((void**)&xn,  g_xn);
    cudaGetSymbolAddress((void**)&cur, g_cur);
    cudaGetSymbolAddress((void**)&x2,  g_x2);
    cudaGetSymbolAddress((void**)&qa,  g_qa);
    cudaGetSymbolAddress((void**)&ka,  g_ka);
    cudaGetSymbolAddress((void**)&vt,  g_vt);
    cudaGetSymbolAddress((void**)&inv, g_inv);
    cudaGetSymbolAddress((void**)&sc,  g_sc);
    cudaGetSymbolAddress((void**)&ph,  g_ph);
    cudaGetSymbolAddress((void**)&hr,  g_hr);
    cudaGetSymbolAddress((void**)&hh,  g_hh);
    cudaGetSymbolAddress((void**)&wqkv,g_wqkv);
    cudaGetSymbolAddress((void**)&wo,  g_wo);
    cudaGetSymbolAddress((void**)&wgu, g_wgu);
    cudaGetSymbolAddress((void**)&wd,  g_wd);

    const int nMD = MM * DD;

    // weights -> fp16 (qkv stacked; gate/up row-interleaved)
    w2h_k<<<(DD*DD/16+255)/256, 256>>>(wqkv,           Wq0, DD*DD/16);
    w2h_k<<<(DD*DD/16+255)/256, 256>>>(wqkv + DD*DD,   Wk0, DD*DD/16);
    w2h_k<<<(DD*DD/16+255)/256, 256>>>(wqkv + 2*DD*DD, Wv0, DD*DD/16);
    w2h_k<<<(DD*DD/16+255)/256, 256>>>(wo,             Wo0, DD*DD/16);
    w2h_glu_k<<<(FF*DD/4+255)/256, 256>>>(wgu, Wg0, Wu0, FF*DD/4);
    w2h_k<<<(FF*DD/16+255)/256, 256>>>(wd,             Wd0, FF*DD/16);

    // pass 1 (accumulates into cur; cur becomes h1 — no copy needed)
    copy_k<<<(nMD+255)/256, 256>>>(cur, x, nMD);
    run_pass(wqkv, wo, wgu, wd, n1, n2, cur, xn, qa, ka, vt, inv, sc, ph, hr, hh);

    // x2 = h1 + beta*(h1 - x)
    x2_k<<<(nMD+255)/256, 256>>>(x2, cur, x, nMD);

    // pass 2 (accumulates into x2)
    run_pass(wqkv, wo, wgu, wd, n3, n4, x2, xn, qa, ka, vt, inv, sc, ph, hr, hh);

    // out = clip(alpha*h1 + (1-alpha)*h2)
    final_k<<<(nMD+255)/256, 256>>>(out, cur, x2, nMD);
}

// round 13
// speedup vs baseline: 1.0518x; 1.0366x over previous
#include <cuda_runtime.h>
#include <cuda_fp16.h>
#include <math.h>
#include <stdint.h>

// ---------------- problem constants ----------------
#define BB   2
#define SS   1024
#define DD   2048
#define HH   16
#define FF   8192
#define DHD  128
#define HALF 64
#define MM   (BB*SS)          // 2048 rows
#define KAUG (2*DHD)          // 256 augmented K dim

#define HS    0.05f
#define BETA  0.3f
#define ALPHA 0.5f
#define CLIPV 10.0f
#define EPSV  1e-6f
#define SCALE 0.08838834764831845f   // 1/sqrt(128)
#define SQLAM 0.31622776601683794f   // sqrt(0.1)

// ---------------- static device scratch ----------------
static __device__ __align__(128) __half g_xn  [MM*DD];          // rmsnorm/mix out (GEMM A)
static __device__ __align__(128) float  g_cur [MM*DD];          // pass-1 residual state (= h1)
static __device__ __align__(128) float  g_x2  [MM*DD];          // pass-2 residual state
static __device__ __align__(128) __half g_qa  [BB*HH*SS*KAUG];
static __device__ __align__(128) __half g_ka  [BB*HH*SS*KAUG];
static __device__ __align__(128) __half g_vt  [BB*HH*DHD*SS];   // per-head [DHD, S]
static __device__ __align__(128) float  g_inv [BB*HH*SS];       // per-row 1/sum
static __device__ __align__(128) __half g_sc  [(long long)BB*HH*SS*SS];  // scores fp16
static __device__ __align__(128) __half g_ph  [(long long)BB*HH*SS*SS];  // unnorm probs fp16
static __device__ __align__(128) __half g_hr  [MM*FF];          // FFN silu(g)*u (unmixed)
static __device__ __align__(128) __half g_hh  [MM*FF];          // FFN hidden mixed (GEMM A)
// fp16 weights
static __device__ __align__(128) __half g_wqkv[3*DD*DD];
static __device__ __align__(128) __half g_wo  [DD*DD];
static __device__ __align__(128) __half g_wgu [2*FF*DD];        // interleaved (gate_j, up_j) rows
static __device__ __align__(128) __half g_wd  [DD*FF];

// ---------------- helpers ----------------
__device__ __forceinline__ uint32_t smem_u32(const void* p) {
    uint32_t a;
    asm("{ .reg .u64 t; cvta.to.shared.u64 t, %1; cvt.u32.u64 %0, t; }" : "=r"(a) : "l"(p));
    return a;
}
__device__ __forceinline__ void cpasync16(uint32_t dst, const void* src) {
    asm volatile("cp.async.cg.shared.global [%0], [%1], 16;" :: "r"(dst), "l"(src));
}
#define CP_COMMIT()  asm volatile("cp.async.commit_group;" ::: "memory")
#define CP_WAIT1()   asm volatile("cp.async.wait_group 1;" ::: "memory")

__device__ __forceinline__ void ldmx4(uint32_t* r, uint32_t addr) {
    asm volatile("ldmatrix.sync.aligned.m8n8.x4.shared.b16 {%0,%1,%2,%3}, [%4];"
        : "=r"(r[0]), "=r"(r[1]), "=r"(r[2]), "=r"(r[3]) : "r"(addr));
}
__device__ __forceinline__ void mma16816(float* c, const uint32_t* a, uint32_t b0, uint32_t b1) {
    asm volatile("mma.sync.aligned.m16n8k16.row.col.f32.f16.f16.f32 "
        "{%0,%1,%2,%3}, {%4,%5,%6,%7}, {%8,%9}, {%0,%1,%2,%3};"
        : "+f"(c[0]), "+f"(c[1]), "+f"(c[2]), "+f"(c[3])
        : "r"(a[0]), "r"(a[1]), "r"(a[2]), "r"(a[3]), "r"(b0), "r"(b1));
}

// ---------------- fp16 tensor-core GEMM with fused epilogues ----------------
// C[M,N](TO) = A[M,K](f16) * B[N,K](f16)^T
// ADD (TO=float): C += acc, or C = addsrc + acc when addsrc != nullptr.
// CTA tile 128x128, chunk = 64 halves (128B rows), 3 smem slots, single-barrier
// mainloop (wait_group 1 + prefetch at top), 2 CTA/SM.
// TRI: blockIdx.x enumerates lower-triangle 128x128 blocks (causal scores).
// PVK: K limited to (blockIdx.y+1)*128 halves (causal PV).
// MIX: PV epilogue — normalize by inv[], hadamard-mix along d, transpose-write fp16 xn.
// QKV: epilogue applies RoPE+augment for q/k head tiles (C=qa / aux1=ka) and
//      transposes v head tiles into aux2=vt. bj in [0,48): 16 q, 16 k, 16 v heads.
// GLU: wgu rows interleaved (gate,up); epilogue computes silu(g)*u from register
//      pairs and writes fp16 [M,F].
#define HSTAGE 32768    // A:128 rows + B:128 rows, 128B each
#define HSMEM  (3*HSTAGE)

template<typename TO, bool ADD, bool TRI, bool PVK, bool MIX, bool QKV, bool GLU>
__global__ void __launch_bounds__(256, 2) hgemm(
    const __half* __restrict__ A, const __half* __restrict__ B, TO* __restrict__ C,
    int Kn, int Nn, long long sA, long long sB, long long sC,
    const float* __restrict__ invp, __half* __restrict__ aux1, __half* __restrict__ aux2,
    const float* __restrict__ addsrc)
{
    extern __shared__ __align__(128) char sm[];
    const uint32_t sbase = smem_u32(sm);

    int bi, bj;
    if (TRI) {
        int x = blockIdx.x, i = 0;
        while ((i + 1) * (i + 2) / 2 <= x) i++;
        bi = i; bj = x - i * (i + 1) / 2;
    } else { bi = blockIdx.y; bj = blockIdx.x; }

    A += (long long)blockIdx.z * sA + (long long)(bi * 128) * Kn;
    B += (long long)blockIdx.z * sB + (long long)(bj * 128) * Kn;
    C += (long long)blockIdx.z * sC;

    const int NC = PVK ? 2 * (blockIdx.y + 1) : (Kn >> 6);

    const int tid = threadIdx.x, warp = tid >> 5, lane = tid & 31;
    const int gid = lane >> 2, tig = lane & 3;
    const int wm = (warp & 3) * 32, wn = (warp >> 2) * 64;

    const int mi = lane >> 3, ri = lane & 7;
    const int fro = (mi & 1) * 8 + ri;
    const int khalf = mi >> 1;

    float acc[2][8][4];
#pragma unroll
    for (int mt = 0; mt < 2; mt++)
#pragma unroll
        for (int nt = 0; nt < 8; nt++)
#pragma unroll
            for (int j = 0; j < 4; j++) acc[mt][nt][j] = 0.f;

    const int lr = tid >> 3;
    const int lseg = tid & 7;

    auto load = [&](int chunk) {
        if (chunk < NC) {
            const uint32_t st = sbase + (uint32_t)(chunk % 3) * HSTAGE;
            const __half* Ag = A + chunk * 64;
            const __half* Bg = B + chunk * 64;
#pragma unroll
            for (int it = 0; it < 4; it++) {
                int r = lr + it * 32;
                uint32_t off = (uint32_t)(r * 128 + ((lseg ^ (r & 7)) << 4));
                cpasync16(st + off,         Ag + (long long)r * Kn + lseg * 8);
                cpasync16(st + 16384 + off, Bg + (long long)r * Kn + lseg * 8);
            }
        }
        CP_COMMIT();
    };

    load(0);
    load(1);

    const int arow[2] = { wm + fro, wm + 16 + fro };
    const int brow[4] = { wn + fro, wn + 16 + fro, wn + 32 + fro, wn + 48 + fro };

    for (int c = 0; c < NC; c++) {
        CP_WAIT1();
        __syncthreads();
        load(c + 2);

        const uint32_t st = sbase + (uint32_t)(c % 3) * HSTAGE;
#pragma unroll
        for (int kb = 0; kb < 64; kb += 16) {
            const int ks = (kb >> 3) + khalf;
            uint32_t a[2][4], b[4][4];
#pragma unroll
            for (int mt = 0; mt < 2; mt++) {
                int r = arow[mt];
                ldmx4(a[mt], st + (uint32_t)(r * 128 + ((ks ^ (r & 7)) << 4)));
            }
#pragma unroll
            for (int np = 0; np < 4; np++) {
                int r = brow[np];
                ldmx4(b[np], st + 16384u + (uint32_t)(r * 128 + ((ks ^ (r & 7)) << 4)));
            }
#pragma unroll
            for (int mt = 0; mt < 2; mt++)
#pragma unroll
                for (int nt = 0; nt < 8; nt++)
                    mma16816(acc[mt][nt], a[mt], b[nt >> 1][nt & 1], b[nt >> 1][2 + (nt & 1)]);
        }
    }

    if constexpr (GLU) {
        __half* hr = (__half*)C;          // stride FF
#pragma unroll
        for (int mt = 0; mt < 2; mt++) {
            int row0 = bi * 128 + wm + mt * 16 + gid;
#pragma unroll
            for (int nt = 0; nt < 8; nt++) {
                int jg = bj * 64 + ((wn + nt * 8) >> 1) + tig;
                float g0 = acc[mt][nt][0], u0 = acc[mt][nt][1];
                float g1 = acc[mt][nt][2], u1 = acc[mt][nt][3];
                hr[(long long)row0 * FF + jg]       = __float2half(g0 / (1.f + __expf(-g0)) * u0);
                hr[(long long)(row0 + 8) * FF + jg] = __float2half(g1 / (1.f + __expf(-g1)) * u1);
            }
        }
        return;
    }

    if constexpr (MIX || QKV) {
        float* stg = (float*)sm;
        __syncthreads();
#pragma unroll
        for (int mt = 0; mt < 2; mt++) {
            int rr = wm + mt * 16 + gid;
#pragma unroll
            for (int nt = 0; nt < 8; nt++) {
                int cc = wn + nt * 8 + 2 * tig;
                stg[rr * 129 + cc]           = acc[mt][nt][0];
                stg[rr * 129 + cc + 1]       = acc[mt][nt][1];
                stg[(rr + 8) * 129 + cc]     = acc[mt][nt][2];
                stg[(rr + 8) * 129 + cc + 1] = acc[mt][nt][3];
            }
        }
        __syncthreads();
    }

    if constexpr (MIX) {
        float* stg = (float*)sm;
        const int bh = blockIdx.z;
        const int b = bh >> 4, h = bh & 15;
        __half* xo = (__half*)C;          // C = xn base (sC == 0)
        for (int i = tid; i < 128 * 128; i += 256) {
            int r = i >> 7, d = i & 127;
            int sg = bi * 128 + r;
            float iv = invp[(long long)bh * SS + sg];
            float v  = stg[r * 129 + d] * iv;
            float pv = stg[r * 129 + ((d + 127) & 127)] * iv;
            xo[((long long)(b * SS + sg)) * DD + h * DHD + d] =
                __float2half(v * (1.f + HS * pv));
        }
        return;
    }

    if constexpr (QKV) {
        float* stg = (float*)sm;
        const int htype = bj >> 4, h = bj & 15;
        const int bq = (bi * 128) >> 10;
        const int s0 = (bi * 128) & 1023;
        if (htype < 2) {
            __half* dst = (htype == 0) ? (__half*)C : aux1;   // qa : ka
            for (int i = tid; i < 128 * 64; i += 256) {
                int r = i >> 6, dd = i & 63;
                int s = s0 + r;
                float v1 = stg[r * 129 + dd];
                float v2 = stg[r * 129 + dd + 64];
                float invf = __expf(-(float)dd * (9.210340371976184f / 64.0f));
                float ang = (float)s * invf;
                float cs, sn; __sincosf(ang, &sn, &cs);
                float o1 = v1 * cs - v2 * sn;
                float o2 = v1 * sn + v2 * cs;
                long long base = (((long long)(bq * HH + h)) * SS + s) * KAUG;
                dst[base + dd]              = __float2half(o1);
                dst[base + HALF + dd]       = __float2half(o2);
                dst[base + DHD + dd]        = __float2half(SQLAM * o1 * o1);
                dst[base + DHD + HALF + dd] = __float2half(SQLAM * o2 * o2);
            }
        } else {
            const int bh = bq * HH + h;
            for (int i = tid; i < 128 * 128; i += 256) {
                int d = i >> 7, sl = i & 127;
                aux2[((long long)(bh * DHD + d)) * SS + s0 + sl] =
                    __float2half(stg[sl * 129 + d]);
            }
        }
        return;
    }

    // standard epilogue
#pragma unroll
    for (int mt = 0; mt < 2; mt++) {
        int r0 = bi * 128 + wm + mt * 16 + gid;
#pragma unroll
        for (int nt = 0; nt < 8; nt++) {
            int cc = bj * 128 + wn + nt * 8 + 2 * tig;
            TO* p0 = C + (long long)r0 * Nn + cc;
            TO* p1 = p0 + 8 * (long long)Nn;
            if constexpr (sizeof(TO) == 2) {
                *(__half2*)p0 = __floats2half2_rn(acc[mt][nt][0], acc[mt][nt][1]);
                *(__half2*)p1 = __floats2half2_rn(acc[mt][nt][2], acc[mt][nt][3]);
            } else if (ADD) {
                if (addsrc) {
                    const float* s0p = addsrc + (long long)r0 * Nn + cc;
                    const float* s1p = s0p + 8 * (long long)Nn;
                    p0[0] = s0p[0] + acc[mt][nt][0]; p0[1] = s0p[1] + acc[mt][nt][1];
                    p1[0] = s1p[0] + acc[mt][nt][2]; p1[1] = s1p[1] + acc[mt][nt][3];
                } else {
                    p0[0] += acc[mt][nt][0]; p0[1] += acc[mt][nt][1];
                    p1[0] += acc[mt][nt][2]; p1[1] += acc[mt][nt][3];
                }
            } else {
                p0[0] = acc[mt][nt][0]; p0[1] = acc[mt][nt][1];
                p1[0] = acc[mt][nt][2]; p1[1] = acc[mt][nt][3];
            }
        }
    }
}

// ---------------- RMSNorm -> fp16 ----------------
__global__ void rmsnorm_k(const float* __restrict__ x, const float* __restrict__ sc,
                          __half* __restrict__ o)
{
    const int row = blockIdx.x;
    const float* xr = x + (long long)row * DD;
    __half*      orw = o + (long long)row * DD;
    float s = 0.f;
    for (int j = threadIdx.x; j < DD; j += 256) { float v = xr[j]; s += v * v; }
    __shared__ float red[256];
    red[threadIdx.x] = s; __syncthreads();
    for (int t = 128; t > 0; t >>= 1) {
        if (threadIdx.x < t) red[threadIdx.x] += red[threadIdx.x + t];
        __syncthreads();
    }
    float r = rsqrtf(red[0] * (1.0f / DD) + EPSV);
    for (int j = threadIdx.x; j < DD; j += 256) orw[j] = __float2half(xr[j] * r * sc[j]);
}

// ---------------- causal softmax (vectorized uint2 = 4 halves per thread) ----------------
__global__ void softmax_k(const __half* __restrict__ sc, __half* __restrict__ ph,
                          float* __restrict__ inv)
{
    long long row = blockIdx.x;
    int i = (int)(row & (SS - 1));
    int lim = i | 127;
    const __half* p = sc + row * SS;
    __half* q = ph + row * SS;
    int tid = threadIdx.x;
    const int j0 = tid * 4;
    __shared__ float red[256];

    __half hv[4];
    if (j0 <= i) *(uint2*)hv = *(const uint2*)(p + j0);

    float v[4];
    float m = -1e30f;
#pragma unroll
    for (int k = 0; k < 4; k++) {
        int j = j0 + k;
        v[k] = (j <= i) ? __half2float(hv[k]) * SCALE : -1e30f;
        m = fmaxf(m, v[k]);
    }
    red[tid] = m; __syncthreads();
    for (int t = 128; t > 0; t >>= 1) {
        if (tid < t) red[tid] = fmaxf(red[tid], red[tid + t]);
        __syncthreads();
    }
    m = red[0]; __syncthreads();

    float sum = 0.f;
    __half e[4];
#pragma unroll
    for (int k = 0; k < 4; k++) {
        int j = j0 + k;
        float ev = (j <= i) ? __expf(v[k] - m) : 0.f;
        e[k] = __float2half(ev);
        sum += ev;
    }
    if (j0 <= lim) *(uint2*)(q + j0) = *(uint2*)e;

    red[tid] = sum; __syncthreads();
    for (int t = 128; t > 0; t >>= 1) {
        if (tid < t) red[tid] += red[tid + t];
        __syncthreads();
    }
    if (tid == 0) inv[row] = 1.f / red[0];
}

// ---------------- FFN hadamard mix (vectorized): hh[c] = hr[c]*(1+HS*hr[c-1]) ----------------
__global__ void mixf_k(const __half* __restrict__ hr, __half* __restrict__ hh)
{
    int t = blockIdx.x * 256 + threadIdx.x;       // M*F/8 threads
    int m = t >> 10;
    int c0 = (t & 1023) << 3;
    const __half* row = hr + (long long)m * FF;
    __half in[8];
    *(uint4*)in = *(const uint4*)(row + c0);
    float hprev = __half2float(row[(c0 + FF - 1) & (FF - 1)]);
    __half outv[8];
#pragma unroll
    for (int k = 0; k < 8; k++) {
        float h = __half2float(in[k]);
        outv[k] = __float2half(h * (1.f + HS * hprev));
        hprev = h;
    }
    *(uint4*)(hh + (long long)m * FF + c0) = *(uint4*)outv;
}

// ---------------- misc elementwise ----------------
// fp32 -> fp16, 1x float4 per thread (n4 = n/4)
__global__ void w2h_k(__half* __restrict__ dst, const float* __restrict__ src, int n4)
{
    int i = blockIdx.x * 256 + threadIdx.x;
    if (i < n4) {
        float4 v = ((const float4*)src)[i];
        __half2 lo = __floats2half2_rn(v.x, v.y);
        __half2 hi = __floats2half2_rn(v.z, v.w);
        ((uint2*)dst)[i] = make_uint2(*(uint32_t*)&lo, *(uint32_t*)&hi);
    }
}

// gate/up interleave conversion: dst row 2j <- Wg row j, row 2j+1 <- Wu row j
__global__ void w2h_glu_k(__half* __restrict__ dst, const float* __restrict__ wg,
                          const float* __restrict__ wu, int n4)   // n4 = FF*DD/4
{
    int e = blockIdx.x * 256 + threadIdx.x;
    if (e < n4) {
        int j = e >> 9, c = e & 511;                 // DD/4 = 512 float4 per row
        float4 vg = ((const float4*)wg)[e];
        float4 vu = ((const float4*)wu)[e];
        __half2 glo = __floats2half2_rn(vg.x, vg.y), ghi = __floats2half2_rn(vg.z, vg.w);
        __half2 ulo = __floats2half2_rn(vu.x, vu.y), uhi = __floats2half2_rn(vu.z, vu.w);
        ((uint2*)dst)[((long long)(2 * j) << 9) + c]     = make_uint2(*(uint32_t*)&glo, *(uint32_t*)&ghi);
        ((uint2*)dst)[((long long)(2 * j + 1) << 9) + c] = make_uint2(*(uint32_t*)&ulo, *(uint32_t*)&uhi);
    }
}

__global__ void x2_k(float* __restrict__ dst, const float* __restrict__ h1,
                     const float* __restrict__ x, int n)
{ int i = blockIdx.x * 256 + threadIdx.x; if (i < n) dst[i] = (1.f + BETA) * h1[i] - BETA * x[i]; }

__global__ void final_k(float* __restrict__ out, const float* __restrict__ h1,
                        const float* __restrict__ h2, int n)
{
    int i = blockIdx.x * 256 + threadIdx.x;
    if (i < n) {
        float v = ALPHA * h1[i] + (1.f - ALPHA) * h2[i];
        out[i] = fminf(fmaxf(v, -CLIPV), CLIPV);
    }
}

// ---------------- host orchestration ----------------
// nsrc: input to the first rmsnorm (x for pass 1, cur for pass 2);
// addsrc: if non-null, Wo epilogue writes cur = addsrc + acc (else cur += acc).
static void run_pass(const __half* wqkv, const __half* wo, const __half* wgu, const __half* wd,
                     const float* na, const float* nb,
                     const float* nsrc, const float* addsrc,
                     float* cur, __half* xn,
                     __half* qa, __half* ka, __half* vt, float* inv,
                     __half* sc, __half* ph, __half* hr, __half* hh)
{
    const int nMF = MM * FF;

    rmsnorm_k<<<MM, 256>>>(nsrc, na, xn);

    // fused QKV + RoPE/augment + V-transpose: writes qa, ka, vt directly
    hgemm<__half,false,false,false,false,true,false><<<dim3(48, MM/128, 1), 256, HSMEM>>>(
        xn, wqkv, qa, DD, 3*DD, 0, 0, 0, nullptr, ka, vt, nullptr);

    // causal scores (fp16 out): lower-triangle blocks only
    hgemm<__half,false,true,false,false,false,false><<<dim3(36, 1, BB*HH), 256, HSMEM>>>(
        qa, ka, sc, KAUG, SS,
        (long long)SS*KAUG, (long long)SS*KAUG, (long long)SS*SS, nullptr, nullptr, nullptr, nullptr);
    softmax_k<<<BB*HH*SS, 256>>>(sc, ph, inv);
    // PV with causal K truncation + fused normalize/mix/transpose epilogue -> xn
    hgemm<__half,false,false,true,true,false,false><<<dim3(1, SS/128, BB*HH), 256, HSMEM>>>(
        ph, vt, xn, SS, DHD,
        (long long)SS*SS, (long long)SS*DHD, 0, inv, nullptr, nullptr, nullptr);

    hgemm<float,true,false,false,false,false,false><<<dim3(DD/128, MM/128, 1), 256, HSMEM>>>(
        xn, wo, cur, DD, DD, 0, 0, 0, nullptr, nullptr, nullptr, addsrc);

    rmsnorm_k<<<MM, 256>>>(cur, nb, xn);
    // fused gate|up (interleaved weights) + silu*up epilogue -> hr [M,F]
    hgemm<__half,false,false,false,false,false,true><<<dim3(2*FF/128, MM/128, 1), 256, HSMEM>>>(
        xn, wgu, hr, DD, 2*FF, 0, 0, 0, nullptr, nullptr, nullptr, nullptr);
    mixf_k<<<nMF/8/256, 256>>>(hr, hh);
    hgemm<float,true,false,false,false,false,false><<<dim3(DD/128, MM/128, 1), 256, HSMEM>>>(
        hh, wd, cur, FF, DD, 0, 0, 0, nullptr, nullptr, nullptr, nullptr);
}

extern "C" void kernel_launch(void* const* d_in, const int* in_sizes, int n_in,
                              void* d_out, int out_size)
{
    (void)in_sizes; (void)n_in; (void)out_size;
    const float* x   = (const float*)d_in[0];
    const float* Wq0 = (const float*)d_in[1];
    const float* Wk0 = (const float*)d_in[2];
    const float* Wv0 = (const float*)d_in[3];
    const float* Wo0 = (const float*)d_in[4];
    // d_in[5] = gate_w: unused (rotate_half invariance => o2 == o1)
    const float* n1 = (const float*)d_in[6];
    const float* n2 = (const float*)d_in[7];
    const float* n3 = (const float*)d_in[8];
    const float* n4 = (const float*)d_in[9];
    const float* Wg0 = (const float*)d_in[10];
    const float* Wu0 = (const float*)d_in[11];
    const float* Wd0 = (const float*)d_in[12];
    float* out = (float*)d_out;

    cudaFuncSetAttribute(hgemm<__half,false,false,false,false,true,false>, cudaFuncAttributeMaxDynamicSharedMemorySize, HSMEM);
    cudaFuncSetAttribute(hgemm<float,true,false,false,false,false,false>,  cudaFuncAttributeMaxDynamicSharedMemorySize, HSMEM);
    cudaFuncSetAttribute(hgemm<__half,false,true,false,false,false,false>, cudaFuncAttributeMaxDynamicSharedMemorySize, HSMEM);
    cudaFuncSetAttribute(hgemm<__half,false,false,true,true,false,false>,  cudaFuncAttributeMaxDynamicSharedMemorySize, HSMEM);
    cudaFuncSetAttribute(hgemm<__half,false,false,false,false,false,true>, cudaFuncAttributeMaxDynamicSharedMemorySize, HSMEM);

    __half *xn, *qa, *ka, *vt, *sc, *ph, *hr, *hh, *wqkv, *wo, *wgu, *wd;
    float *cur, *x2, *inv;
    cudaGetSymbolAddress((void**)&xn,  g_xn);
    cudaGetSymbolAddress((void**)&cur, g_cur);
    cudaGetSymbolAddress((void**)&x2,  g_x2);
    cudaGetSymbolAddress((void**)&qa,  g_qa);
    cudaGetSymbolAddress((void**)&ka,  g_ka);
    cudaGetSymbolAddress((void**)&vt,  g_vt);
    cudaGetSymbolAddress((void**)&inv, g_inv);
    cudaGetSymbolAddress((void**)&sc,  g_sc);
    cudaGetSymbolAddress((void**)&ph,  g_ph);
    cudaGetSymbolAddress((void**)&hr,  g_hr);
    cudaGetSymbolAddress((void**)&hh,  g_hh);
    cudaGetSymbolAddress((void**)&wqkv,g_wqkv);
    cudaGetSymbolAddress((void**)&wo,  g_wo);
    cudaGetSymbolAddress((void**)&wgu, g_wgu);
    cudaGetSymbolAddress((void**)&wd,  g_wd);

    const int nMD = MM * DD;

    // weights -> fp16 (qkv stacked; gate/up row-interleaved); 1 float4/thread
    w2h_k<<<(DD*DD/4+255)/256, 256>>>(wqkv,           Wq0, DD*DD/4);
    w2h_k<<<(DD*DD/4+255)/256, 256>>>(wqkv + DD*DD,   Wk0, DD*DD/4);
    w2h_k<<<(DD*DD/4+255)/256, 256>>>(wqkv + 2*DD*DD, Wv0, DD*DD/4);
    w2h_k<<<(DD*DD/4+255)/256, 256>>>(wo,             Wo0, DD*DD/4);
    w2h_glu_k<<<(FF*DD/4+255)/256, 256>>>(wgu, Wg0, Wu0, FF*DD/4);
    w2h_k<<<(FF*DD/4+255)/256, 256>>>(wd,             Wd0, FF*DD/4);

    // pass 1: rmsnorm reads x; Wo epilogue initializes cur = x + attn (no copy)
    run_pass(wqkv, wo, wgu, wd, n1, n2, x, x,
             cur, xn, qa, ka, vt, inv, sc, ph, hr, hh);

    // x2 = h1 + beta*(h1 - x)
    x2_k<<<(nMD+255)/256, 256>>>(x2, cur, x, nMD);

    // pass 2: rmsnorm reads x2; Wo epilogue accumulates into x2
    run_pass(wqkv, wo, wgu, wd, n3, n4, x2, nullptr,
             x2, xn, qa, ka, vt, inv, sc, ph, hr, hh);

    // out = clip(alpha*h1 + (1-alpha)*h2)
    final_k<<<(nMD+255)/256, 256>>>(out, cur, x2, nMD);
}

// round 14
// speedup vs baseline: 1.0963x; 1.0423x over previous
#include <cuda_runtime.h>
#include <cuda_fp16.h>
#include <math.h>
#include <stdint.h>

// ---------------- problem constants ----------------
#define BB   2
#define SS   1024
#define DD   2048
#define HH   16
#define FF   8192
#define DHD  128
#define HALF 64
#define MM   (BB*SS)          // 2048 rows
#define KAUG (2*DHD)          // 256 augmented K dim

#define HS    0.05f
#define BETA  0.3f
#define ALPHA 0.5f
#define CLIPV 10.0f
#define EPSV  1e-6f
#define SCALE 0.08838834764831845f   // 1/sqrt(128)
#define SQLAM 0.31622776601683794f   // sqrt(0.1)
#define ESHIFT 4.0f                  // fixed softmax shift (cancels in normalization)

// ---------------- static device scratch ----------------
static __device__ __align__(128) __half g_xn  [MM*DD];          // rmsnorm/mix out (GEMM A)
static __device__ __align__(128) float  g_cur [MM*DD];          // pass-1 residual state (= h1)
static __device__ __align__(128) float  g_x2  [MM*DD];          // pass-2 residual state
static __device__ __align__(128) __half g_qa  [BB*HH*SS*KAUG];
static __device__ __align__(128) __half g_ka  [BB*HH*SS*KAUG];
static __device__ __align__(128) __half g_vt  [BB*HH*DHD*SS];   // per-head [DHD, S]
static __device__ __align__(128) float  g_inv [BB*HH*SS];       // row sums -> 1/sum
static __device__ __align__(128) __half g_ph  [(long long)BB*HH*SS*SS];  // unnorm probs fp16
static __device__ __align__(128) __half g_hr  [MM*FF];          // FFN silu(g)*u (unmixed)
static __device__ __align__(128) __half g_hh  [MM*FF];          // FFN hidden mixed (GEMM A)
// fp16 weights
static __device__ __align__(128) __half g_wqkv[3*DD*DD];
static __device__ __align__(128) __half g_wo  [DD*DD];
static __device__ __align__(128) __half g_wgu [2*FF*DD];        // interleaved (gate_j, up_j) rows
static __device__ __align__(128) __half g_wd  [DD*FF];

// ---------------- helpers ----------------
__device__ __forceinline__ uint32_t smem_u32(const void* p) {
    uint32_t a;
    asm("{ .reg .u64 t; cvta.to.shared.u64 t, %1; cvt.u32.u64 %0, t; }" : "=r"(a) : "l"(p));
    return a;
}
__device__ __forceinline__ void cpasync16(uint32_t dst, const void* src) {
    asm volatile("cp.async.cg.shared.global [%0], [%1], 16;" :: "r"(dst), "l"(src));
}
#define CP_COMMIT()  asm volatile("cp.async.commit_group;" ::: "memory")
#define CP_WAIT1()   asm volatile("cp.async.wait_group 1;" ::: "memory")

__device__ __forceinline__ void ldmx4(uint32_t* r, uint32_t addr) {
    asm volatile("ldmatrix.sync.aligned.m8n8.x4.shared.b16 {%0,%1,%2,%3}, [%4];"
        : "=r"(r[0]), "=r"(r[1]), "=r"(r[2]), "=r"(r[3]) : "r"(addr));
}
__device__ __forceinline__ void mma16816(float* c, const uint32_t* a, uint32_t b0, uint32_t b1) {
    asm volatile("mma.sync.aligned.m16n8k16.row.col.f32.f16.f16.f32 "
        "{%0,%1,%2,%3}, {%4,%5,%6,%7}, {%8,%9}, {%0,%1,%2,%3};"
        : "+f"(c[0]), "+f"(c[1]), "+f"(c[2]), "+f"(c[3])
        : "r"(a[0]), "r"(a[1]), "r"(a[2]), "r"(a[3]), "r"(b0), "r"(b1));
}

// ---------------- fp16 tensor-core GEMM with fused epilogues ----------------
// C[M,N](TO) = A[M,K](f16) * B[N,K](f16)^T
// ADD (TO=float): C += acc, or C = addsrc + acc when addsrc != nullptr.
// CTA tile 128x128, chunk = 64 halves (128B rows), 3 smem slots, single-barrier
// mainloop, 2 CTA/SM.
// TRI: blockIdx.x enumerates lower-triangle 128x128 blocks (causal scores).
// PVK: K limited to (blockIdx.y+1)*128 halves (causal PV).
// MIX: PV epilogue — normalize by inv[], hadamard-mix along d, transpose-write fp16 xn.
// QKV: RoPE+augment epilogue for q/k heads (C=qa / aux1=ka), v transpose into aux2=vt.
// GLU: interleaved gate/up weights; epilogue writes silu(g)*u fp16 [M,F].
// SMAX: scores epilogue — e = exp(acc*SCALE - ESHIFT) with causal mask, write
//       fp16 ph directly, atomicAdd per-row partial sums into invp (as sums).
#define HSTAGE 32768    // A:128 rows + B:128 rows, 128B each
#define HSMEM  (3*HSTAGE)
#define STGN   (128*129)   // fp32 staging floats (66048 B)

template<typename TO, bool ADD, bool TRI, bool PVK, bool MIX, bool QKV, bool GLU, bool SMAX>
__global__ void __launch_bounds__(256, 2) hgemm(
    const __half* __restrict__ A, const __half* __restrict__ B, TO* __restrict__ C,
    int Kn, int Nn, long long sA, long long sB, long long sC,
    float* __restrict__ invp, __half* __restrict__ aux1, __half* __restrict__ aux2,
    const float* __restrict__ addsrc)
{
    extern __shared__ __align__(128) char sm[];
    const uint32_t sbase = smem_u32(sm);

    int bi, bj;
    if (TRI) {
        int x = blockIdx.x, i = 0;
        while ((i + 1) * (i + 2) / 2 <= x) i++;
        bi = i; bj = x - i * (i + 1) / 2;
    } else { bi = blockIdx.y; bj = blockIdx.x; }

    A += (long long)blockIdx.z * sA + (long long)(bi * 128) * Kn;
    B += (long long)blockIdx.z * sB + (long long)(bj * 128) * Kn;
    C += (long long)blockIdx.z * sC;

    const int NC = PVK ? 2 * (blockIdx.y + 1) : (Kn >> 6);

    const int tid = threadIdx.x, warp = tid >> 5, lane = tid & 31;
    const int gid = lane >> 2, tig = lane & 3;
    const int wm = (warp & 3) * 32, wn = (warp >> 2) * 64;

    const int mi = lane >> 3, ri = lane & 7;
    const int fro = (mi & 1) * 8 + ri;
    const int khalf = mi >> 1;

    float acc[2][8][4];
#pragma unroll
    for (int mt = 0; mt < 2; mt++)
#pragma unroll
        for (int nt = 0; nt < 8; nt++)
#pragma unroll
            for (int j = 0; j < 4; j++) acc[mt][nt][j] = 0.f;

    const int lr = tid >> 3;
    const int lseg = tid & 7;

    auto load = [&](int chunk) {
        if (chunk < NC) {
            const uint32_t st = sbase + (uint32_t)(chunk % 3) * HSTAGE;
            const __half* Ag = A + chunk * 64;
            const __half* Bg = B + chunk * 64;
#pragma unroll
            for (int it = 0; it < 4; it++) {
                int r = lr + it * 32;
                uint32_t off = (uint32_t)(r * 128 + ((lseg ^ (r & 7)) << 4));
                cpasync16(st + off,         Ag + (long long)r * Kn + lseg * 8);
                cpasync16(st + 16384 + off, Bg + (long long)r * Kn + lseg * 8);
            }
        }
        CP_COMMIT();
    };

    load(0);
    load(1);

    const int arow[2] = { wm + fro, wm + 16 + fro };
    const int brow[4] = { wn + fro, wn + 16 + fro, wn + 32 + fro, wn + 48 + fro };

    for (int c = 0; c < NC; c++) {
        CP_WAIT1();
        __syncthreads();
        load(c + 2);

        const uint32_t st = sbase + (uint32_t)(c % 3) * HSTAGE;
#pragma unroll
        for (int kb = 0; kb < 64; kb += 16) {
            const int ks = (kb >> 3) + khalf;
            uint32_t a[2][4], b[4][4];
#pragma unroll
            for (int mt = 0; mt < 2; mt++) {
                int r = arow[mt];
                ldmx4(a[mt], st + (uint32_t)(r * 128 + ((ks ^ (r & 7)) << 4)));
            }
#pragma unroll
            for (int np = 0; np < 4; np++) {
                int r = brow[np];
                ldmx4(b[np], st + 16384u + (uint32_t)(r * 128 + ((ks ^ (r & 7)) << 4)));
            }
#pragma unroll
            for (int mt = 0; mt < 2; mt++)
#pragma unroll
                for (int nt = 0; nt < 8; nt++)
                    mma16816(acc[mt][nt], a[mt], b[nt >> 1][nt & 1], b[nt >> 1][2 + (nt & 1)]);
        }
    }

    if constexpr (GLU) {
        __half* hr = (__half*)C;          // stride FF
#pragma unroll
        for (int mt = 0; mt < 2; mt++) {
            int row0 = bi * 128 + wm + mt * 16 + gid;
#pragma unroll
            for (int nt = 0; nt < 8; nt++) {
                int jg = bj * 64 + ((wn + nt * 8) >> 1) + tig;
                float g0 = acc[mt][nt][0], u0 = acc[mt][nt][1];
                float g1 = acc[mt][nt][2], u1 = acc[mt][nt][3];
                hr[(long long)row0 * FF + jg]       = __float2half(g0 / (1.f + __expf(-g0)) * u0);
                hr[(long long)(row0 + 8) * FF + jg] = __float2half(g1 / (1.f + __expf(-g1)) * u1);
            }
        }
        return;
    }

    if constexpr (MIX || QKV || SMAX) {
        float* stg = (float*)sm;
        __syncthreads();
#pragma unroll
        for (int mt = 0; mt < 2; mt++) {
            int rr = wm + mt * 16 + gid;
#pragma unroll
            for (int nt = 0; nt < 8; nt++) {
                int cc = wn + nt * 8 + 2 * tig;
                stg[rr * 129 + cc]           = acc[mt][nt][0];
                stg[rr * 129 + cc + 1]       = acc[mt][nt][1];
                stg[(rr + 8) * 129 + cc]     = acc[mt][nt][2];
                stg[(rr + 8) * 129 + cc + 1] = acc[mt][nt][3];
            }
        }
        __syncthreads();
    }

    if constexpr (SMAX) {
        // fused softmax (fixed shift): e = exp(s*SCALE - ESHIFT), causal mask,
        // fp16 write to ph + per-row sum atomicAdd into invp (sums).
        float* stg = (float*)sm;
        float* sred = (float*)(sm + STGN * 4);    // 256 floats after staging
        const int bh = blockIdx.z;
        const int r = tid >> 1, c0 = (tid & 1) * 64;
        const int qi = bi * 128 + r;
        __half* dst = (__half*)C + (long long)qi * SS + bj * 128 + c0;
        float sum = 0.f;
#pragma unroll
        for (int k = 0; k < 64; k += 8) {
            __half ev[8];
#pragma unroll
            for (int u = 0; u < 8; u++) {
                int kj = bj * 128 + c0 + k + u;
                float e = (kj <= qi) ? __expf(stg[r * 129 + c0 + k + u] * SCALE - ESHIFT) : 0.f;
                ev[u] = __float2half(e);
                sum += e;
            }
            *(uint4*)(dst + k) = *(uint4*)ev;
        }
        sred[tid] = sum;
        __syncthreads();
        if (tid < 128)
            atomicAdd(&invp[(long long)bh * SS + bi * 128 + tid],
                      sred[2 * tid] + sred[2 * tid + 1]);
        return;
    }

    if constexpr (MIX) {
        float* stg = (float*)sm;
        const int bh = blockIdx.z;
        const int b = bh >> 4, h = bh & 15;
        __half* xo = (__half*)C;          // C = xn base (sC == 0)
        for (int i = tid; i < 128 * 128; i += 256) {
            int r = i >> 7, d = i & 127;
            int sg = bi * 128 + r;
            float iv = invp[(long long)bh * SS + sg];
            float v  = stg[r * 129 + d] * iv;
            float pv = stg[r * 129 + ((d + 127) & 127)] * iv;
            xo[((long long)(b * SS + sg)) * DD + h * DHD + d] =
                __float2half(v * (1.f + HS * pv));
        }
        return;
    }

    if constexpr (QKV) {
        float* stg = (float*)sm;
        const int htype = bj >> 4, h = bj & 15;
        const int bq = (bi * 128) >> 10;
        const int s0 = (bi * 128) & 1023;
        if (htype < 2) {
            __half* dst = (htype == 0) ? (__half*)C : aux1;   // qa : ka
            for (int i = tid; i < 128 * 64; i += 256) {
                int r = i >> 6, dd = i & 63;
                int s = s0 + r;
                float v1 = stg[r * 129 + dd];
                float v2 = stg[r * 129 + dd + 64];
                float invf = __expf(-(float)dd * (9.210340371976184f / 64.0f));
                float ang = (float)s * invf;
                float cs, sn; __sincosf(ang, &sn, &cs);
                float o1 = v1 * cs - v2 * sn;
                float o2 = v1 * sn + v2 * cs;
                long long base = (((long long)(bq * HH + h)) * SS + s) * KAUG;
                dst[base + dd]              = __float2half(o1);
                dst[base + HALF + dd]       = __float2half(o2);
                dst[base + DHD + dd]        = __float2half(SQLAM * o1 * o1);
                dst[base + DHD + HALF + dd] = __float2half(SQLAM * o2 * o2);
            }
        } else {
            const int bh = bq * HH + h;
            for (int i = tid; i < 128 * 128; i += 256) {
                int d = i >> 7, sl = i & 127;
                aux2[((long long)(bh * DHD + d)) * SS + s0 + sl] =
                    __float2half(stg[sl * 129 + d]);
            }
        }
        return;
    }

    // standard epilogue
#pragma unroll
    for (int mt = 0; mt < 2; mt++) {
        int r0 = bi * 128 + wm + mt * 16 + gid;
#pragma unroll
        for (int nt = 0; nt < 8; nt++) {
            int cc = bj * 128 + wn + nt * 8 + 2 * tig;
            TO* p0 = C + (long long)r0 * Nn + cc;
            TO* p1 = p0 + 8 * (long long)Nn;
            if constexpr (sizeof(TO) == 2) {
                *(__half2*)p0 = __floats2half2_rn(acc[mt][nt][0], acc[mt][nt][1]);
                *(__half2*)p1 = __floats2half2_rn(acc[mt][nt][2], acc[mt][nt][3]);
            } else if (ADD) {
                if (addsrc) {
                    const float* s0p = addsrc + (long long)r0 * Nn + cc;
                    const float* s1p = s0p + 8 * (long long)Nn;
                    p0[0] = s0p[0] + acc[mt][nt][0]; p0[1] = s0p[1] + acc[mt][nt][1];
                    p1[0] = s1p[0] + acc[mt][nt][2]; p1[1] = s1p[1] + acc[mt][nt][3];
                } else {
                    p0[0] += acc[mt][nt][0]; p0[1] += acc[mt][nt][1];
                    p1[0] += acc[mt][nt][2]; p1[1] += acc[mt][nt][3];
                }
            } else {
                p0[0] = acc[mt][nt][0]; p0[1] = acc[mt][nt][1];
                p1[0] = acc[mt][nt][2]; p1[1] = acc[mt][nt][3];
            }
        }
    }
}

// ---------------- RMSNorm -> fp16 ----------------
__global__ void rmsnorm_k(const float* __restrict__ x, const float* __restrict__ sc,
                          __half* __restrict__ o)
{
    const int row = blockIdx.x;
    const float* xr = x + (long long)row * DD;
    __half*      orw = o + (long long)row * DD;
    float s = 0.f;
    for (int j = threadIdx.x; j < DD; j += 256) { float v = xr[j]; s += v * v; }
    __shared__ float red[256];
    red[threadIdx.x] = s; __syncthreads();
    for (int t = 128; t > 0; t >>= 1) {
        if (threadIdx.x < t) red[threadIdx.x] += red[threadIdx.x + t];
        __syncthreads();
    }
    float r = rsqrtf(red[0] * (1.0f / DD) + EPSV);
    for (int j = threadIdx.x; j < DD; j += 256) orw[j] = __float2half(xr[j] * r * sc[j]);
}

// ---------------- FFN hadamard mix (vectorized): hh[c] = hr[c]*(1+HS*hr[c-1]) ----------------
__global__ void mixf_k(const __half* __restrict__ hr, __half* __restrict__ hh)
{
    int t = blockIdx.x * 256 + threadIdx.x;       // M*F/8 threads
    int m = t >> 10;
    int c0 = (t & 1023) << 3;
    const __half* row = hr + (long long)m * FF;
    __half in[8];
    *(uint4*)in = *(const uint4*)(row + c0);
    float hprev = __half2float(row[(c0 + FF - 1) & (FF - 1)]);
    __half outv[8];
#pragma unroll
    for (int k = 0; k < 8; k++) {
        float h = __half2float(in[k]);
        outv[k] = __float2half(h * (1.f + HS * hprev));
        hprev = h;
    }
    *(uint4*)(hh + (long long)m * FF + c0) = *(uint4*)outv;
}

// ---------------- misc elementwise ----------------
__global__ void zero_k(float* __restrict__ p, int n)
{ int i = blockIdx.x * 256 + threadIdx.x; if (i < n) p[i] = 0.f; }

__global__ void recip_k(float* __restrict__ p, int n)
{ int i = blockIdx.x * 256 + threadIdx.x; if (i < n) p[i] = 1.f / p[i]; }

// fp32 -> fp16, 1x float4 per thread (n4 = n/4)
__global__ void w2h_k(__half* __restrict__ dst, const float* __restrict__ src, int n4)
{
    int i = blockIdx.x * 256 + threadIdx.x;
    if (i < n4) {
        float4 v = ((const float4*)src)[i];
        __half2 lo = __floats2half2_rn(v.x, v.y);
        __half2 hi = __floats2half2_rn(v.z, v.w);
        ((uint2*)dst)[i] = make_uint2(*(uint32_t*)&lo, *(uint32_t*)&hi);
    }
}

// gate/up interleave conversion: dst row 2j <- Wg row j, row 2j+1 <- Wu row j
__global__ void w2h_glu_k(__half* __restrict__ dst, const float* __restrict__ wg,
                          const float* __restrict__ wu, int n4)   // n4 = FF*DD/4
{
    int e = blockIdx.x * 256 + threadIdx.x;
    if (e < n4) {
        int j = e >> 9, c = e & 511;                 // DD/4 = 512 float4 per row
        float4 vg = ((const float4*)wg)[e];
        float4 vu = ((const float4*)wu)[e];
        __half2 glo = __floats2half2_rn(vg.x, vg.y), ghi = __floats2half2_rn(vg.z, vg.w);
        __half2 ulo = __floats2half2_rn(vu.x, vu.y), uhi = __floats2half2_rn(vu.z, vu.w);
        ((uint2*)dst)[((long long)(2 * j) << 9) + c]     = make_uint2(*(uint32_t*)&glo, *(uint32_t*)&ghi);
        ((uint2*)dst)[((long long)(2 * j + 1) << 9) + c] = make_uint2(*(uint32_t*)&ulo, *(uint32_t*)&uhi);
    }
}

__global__ void x2_k(float* __restrict__ dst, const float* __restrict__ h1,
                     const float* __restrict__ x, int n)
{ int i = blockIdx.x * 256 + threadIdx.x; if (i < n) dst[i] = (1.f + BETA) * h1[i] - BETA * x[i]; }

__global__ void final_k(float* __restrict__ out, const float* __restrict__ h1,
                        const float* __restrict__ h2, int n)
{
    int i = blockIdx.x * 256 + threadIdx.x;
    if (i < n) {
        float v = ALPHA * h1[i] + (1.f - ALPHA) * h2[i];
        out[i] = fminf(fmaxf(v, -CLIPV), CLIPV);
    }
}

// ---------------- host orchestration ----------------
static void run_pass(const __half* wqkv, const __half* wo, const __half* wgu, const __half* wd,
                     const float* na, const float* nb,
                     const float* nsrc, const float* addsrc,
                     float* cur, __half* xn,
                     __half* qa, __half* ka, __half* vt, float* inv,
                     __half* ph, __half* hr, __half* hh)
{
    const int nMF = MM * FF, nInv = BB * HH * SS;

    rmsnorm_k<<<MM, 256>>>(nsrc, na, xn);

    // fused QKV + RoPE/augment + V-transpose: writes qa, ka, vt directly
    hgemm<__half,false,false,false,false,true,false,false><<<dim3(48, MM/128, 1), 256, HSMEM>>>(
        xn, wqkv, qa, DD, 3*DD, 0, 0, 0, nullptr, ka, vt, nullptr);

    // causal scores + fused shifted-exp softmax epilogue -> ph + row sums
    zero_k<<<(nInv+255)/256, 256>>>(inv, nInv);
    hgemm<__half,false,true,false,false,false,false,true><<<dim3(36, 1, BB*HH), 256, HSMEM>>>(
        qa, ka, ph, KAUG, SS,
        (long long)SS*KAUG, (long long)SS*KAUG, (long long)SS*SS, inv, nullptr, nullptr, nullptr);
    recip_k<<<(nInv+255)/256, 256>>>(inv, nInv);

    // PV with causal K truncation + fused normalize/mix/transpose epilogue -> xn
    hgemm<__half,false,false,true,true,false,false,false><<<dim3(1, SS/128, BB*HH), 256, HSMEM>>>(
        ph, vt, xn, SS, DHD,
        (long long)SS*SS, (long long)SS*DHD, 0, inv, nullptr, nullptr, nullptr);

    hgemm<float,true,false,false,false,false,false,false><<<dim3(DD/128, MM/128, 1), 256, HSMEM>>>(
        xn, wo, cur, DD, DD, 0, 0, 0, nullptr, nullptr, nullptr, addsrc);

    rmsnorm_k<<<MM, 256>>>(cur, nb, xn);
    // fused gate|up (interleaved weights) + silu*up epilogue -> hr [M,F]
    hgemm<__half,false,false,false,false,false,true,false><<<dim3(2*FF/128, MM/128, 1), 256, HSMEM>>>(
        xn, wgu, hr, DD, 2*FF, 0, 0, 0, nullptr, nullptr, nullptr, nullptr);
    mixf_k<<<nMF/8/256, 256>>>(hr, hh);
    hgemm<float,true,false,false,false,false,false,false><<<dim3(DD/128, MM/128, 1), 256, HSMEM>>>(
        hh, wd, cur, FF, DD, 0, 0, 0, nullptr, nullptr, nullptr, nullptr);
}

extern "C" void kernel_launch(void* const* d_in, const int* in_sizes, int n_in,
                              void* d_out, int out_size)
{
    (void)in_sizes; (void)n_in; (void)out_size;
    const float* x   = (const float*)d_in[0];
    const float* Wq0 = (const float*)d_in[1];
    const float* Wk0 = (const float*)d_in[2];
    const float* Wv0 = (const float*)d_in[3];
    const float* Wo0 = (const float*)d_in[4];
    // d_in[5] = gate_w: unused (rotate_half invariance => o2 == o1)
    const float* n1 = (const float*)d_in[6];
    const float* n2 = (const float*)d_in[7];
    const float* n3 = (const float*)d_in[8];
    const float* n4 = (const float*)d_in[9];
    const float* Wg0 = (const float*)d_in[10];
    const float* Wu0 = (const float*)d_in[11];
    const float* Wd0 = (const float*)d_in[12];
    float* out = (float*)d_out;

    cudaFuncSetAttribute(hgemm<__half,false,false,false,false,true,false,false>, cudaFuncAttributeMaxDynamicSharedMemorySize, HSMEM);
    cudaFuncSetAttribute(hgemm<float,true,false,false,false,false,false,false>,  cudaFuncAttributeMaxDynamicSharedMemorySize, HSMEM);
    cudaFuncSetAttribute(hgemm<__half,false,true,false,false,false,false,true>,  cudaFuncAttributeMaxDynamicSharedMemorySize, HSMEM);
    cudaFuncSetAttribute(hgemm<__half,false,false,true,true,false,false,false>,  cudaFuncAttributeMaxDynamicSharedMemorySize, HSMEM);
    cudaFuncSetAttribute(hgemm<__half,false,false,false,false,false,true,false>, cudaFuncAttributeMaxDynamicSharedMemorySize, HSMEM);

    __half *xn, *qa, *ka, *vt, *ph, *hr, *hh, *wqkv, *wo, *wgu, *wd;
    float *cur, *x2, *inv;
    cudaGetSymbolAddress((void**)&xn,  g_xn);
    cudaGetSymbolAddress((void**)&cur, g_cur);
    cudaGetSymbolAddress((void**)&x2,  g_x2);
    cudaGetSymbolAddress((void**)&qa,  g_qa);
    cudaGetSymbolAddress((void**)&ka,  g_ka);
    cudaGetSymbolAddress((void**)&vt,  g_vt);
    cudaGetSymbolAddress((void**)&inv, g_inv);
    cudaGetSymbolAddress((void**)&ph,  g_ph);
    cudaGetSymbolAddress((void**)&hr,  g_hr);
    cudaGetSymbolAddress((void**)&hh,  g_hh);
    cudaGetSymbolAddress((void**)&wqkv,g_wqkv);
    cudaGetSymbolAddress((void**)&wo,  g_wo);
    cudaGetSymbolAddress((void**)&wgu, g_wgu);
    cudaGetSymbolAddress((void**)&wd,  g_wd);

    const int nMD = MM * DD;

    // weights -> fp16 (qkv stacked; gate/up row-interleaved); 1 float4/thread
    w2h_k<<<(DD*DD/4+255)/256, 256>>>(wqkv,           Wq0, DD*DD/4);
    w2h_k<<<(DD*DD/4+255)/256, 256>>>(wqkv + DD*DD,   Wk0, DD*DD/4);
    w2h_k<<<(DD*DD/4+255)/256, 256>>>(wqkv + 2*DD*DD, Wv0, DD*DD/4);
    w2h_k<<<(DD*DD/4+255)/256, 256>>>(wo,             Wo0, DD*DD/4);
    w2h_glu_k<<<(FF*DD/4+255)/256, 256>>>(wgu, Wg0, Wu0, FF*DD/4);
    w2h_k<<<(FF*DD/4+255)/256, 256>>>(wd,             Wd0, FF*DD/4);

    // pass 1: rmsnorm reads x; Wo epilogue initializes cur = x + attn (no copy)
    run_pass(wqkv, wo, wgu, wd, n1, n2, x, x,
             cur, xn, qa, ka, vt, inv, ph, hr, hh);

    // x2 = h1 + beta*(h1 - x)
    x2_k<<<(nMD+255)/256, 256>>>(x2, cur, x, nMD);

    // pass 2: rmsnorm reads x2; Wo epilogue accumulates into x2
    run_pass(wqkv, wo, wgu, wd, n3, n4, x2, nullptr,
             x2, xn, qa, ka, vt, inv, ph, hr, hh);

    // out = clip(alpha*h1 + (1-alpha)*h2)
    final_k<<<(nMD+255)/256, 256>>>(out, cur, x2, nMD);
}

// round 15
// speedup vs baseline: 1.1211x; 1.0226x over previous
#include <cuda_runtime.h>
#include <cuda_fp16.h>
#include <math.h>
#include <stdint.h>

// ---------------- problem constants ----------------
#define BB   2
#define SS   1024
#define DD   2048
#define HH   16
#define FF   8192
#define DHD  128
#define HALF 64
#define MM   (BB*SS)          // 2048 rows
#define KAUG (2*DHD)          // 256 augmented K dim

#define HS    0.05f
#define BETA  0.3f
#define ALPHA 0.5f
#define CLIPV 10.0f
#define EPSV  1e-6f
#define SCALE 0.08838834764831845f   // 1/sqrt(128)
#define SQLAM 0.31622776601683794f   // sqrt(0.1)
#define ESHIFT 4.0f                  // fixed softmax shift (cancels in normalization)

// ---------------- static device scratch ----------------
static __device__ __align__(128) __half g_xn  [MM*DD];          // rmsnorm/mix out (GEMM A)
static __device__ __align__(128) float  g_cur [MM*DD];          // pass-1 residual state (= h1)
static __device__ __align__(128) float  g_x2  [MM*DD];          // pass-2 residual state
static __device__ __align__(128) __half g_qa  [BB*HH*SS*KAUG];
static __device__ __align__(128) __half g_ka  [BB*HH*SS*KAUG];
static __device__ __align__(128) __half g_vt  [BB*HH*DHD*SS];   // per-head [DHD, S]
static __device__ __align__(128) float  g_inv [BB*HH*SS];       // row sums -> 1/sum
static __device__ __align__(128) __half g_ph  [(long long)BB*HH*SS*SS];  // unnorm probs fp16
static __device__ __align__(128) __half g_hr  [MM*FF];          // FFN silu(g)*u (unmixed)
static __device__ __align__(128) __half g_hh  [MM*FF];          // FFN hidden mixed (GEMM A)
// fp16 weights
static __device__ __align__(128) __half g_wqkv[3*DD*DD];
static __device__ __align__(128) __half g_wo  [DD*DD];
static __device__ __align__(128) __half g_wgu [2*FF*DD];        // interleaved (gate_j, up_j) rows
static __device__ __align__(128) __half g_wd  [DD*FF];

// ---------------- helpers ----------------
__device__ __forceinline__ uint32_t smem_u32(const void* p) {
    uint32_t a;
    asm("{ .reg .u64 t; cvta.to.shared.u64 t, %1; cvt.u32.u64 %0, t; }" : "=r"(a) : "l"(p));
    return a;
}
__device__ __forceinline__ void cpasync16(uint32_t dst, const void* src) {
    asm volatile("cp.async.cg.shared.global [%0], [%1], 16;" :: "r"(dst), "l"(src));
}
#define CP_COMMIT()  asm volatile("cp.async.commit_group;" ::: "memory")
#define CP_WAIT1()   asm volatile("cp.async.wait_group 1;" ::: "memory")

__device__ __forceinline__ void ldmx4(uint32_t* r, uint32_t addr) {
    asm volatile("ldmatrix.sync.aligned.m8n8.x4.shared.b16 {%0,%1,%2,%3}, [%4];"
        : "=r"(r[0]), "=r"(r[1]), "=r"(r[2]), "=r"(r[3]) : "r"(addr));
}
__device__ __forceinline__ void mma16816(float* c, const uint32_t* a, uint32_t b0, uint32_t b1) {
    asm volatile("mma.sync.aligned.m16n8k16.row.col.f32.f16.f16.f32 "
        "{%0,%1,%2,%3}, {%4,%5,%6,%7}, {%8,%9}, {%0,%1,%2,%3};"
        : "+f"(c[0]), "+f"(c[1]), "+f"(c[2]), "+f"(c[3])
        : "r"(a[0]), "r"(a[1]), "r"(a[2]), "r"(a[3]), "r"(b0), "r"(b1));
}
__device__ __forceinline__ uint2 f4_to_h4(float4 v) {
    __half2 lo = __floats2half2_rn(v.x, v.y);
    __half2 hi = __floats2half2_rn(v.z, v.w);
    return make_uint2(*(uint32_t*)&lo, *(uint32_t*)&hi);
}

// ---------------- fp16 tensor-core GEMM with fused epilogues ----------------
// C[M,N](TO) = A[M,K](f16) * B[N,K](f16)^T
// ADD (TO=float): C += acc, or C = addsrc + acc when addsrc != nullptr.
// CTA tile 128x128, chunk = 64 halves (128B rows), 3 smem slots, single-barrier
// mainloop, 2 CTA/SM.
// TRI: blockIdx.x enumerates lower-triangle 128x128 blocks (causal scores).
// PVK: K limited to (blockIdx.y+1)*128 halves (causal PV).
// MIX: PV epilogue — normalize by inv[], hadamard-mix along d, transpose-write fp16 xn.
// QKV: RoPE+augment epilogue for q/k heads (C=qa / aux1=ka), v transpose into aux2=vt.
// GLU: interleaved gate/up weights; epilogue writes silu(g)*u fp16 [M,F].
// SMAX: scores epilogue — e = exp(acc*SCALE - ESHIFT) with causal mask, write
//       fp16 ph directly, atomicAdd per-row partial sums into invp (as sums).
#define HSTAGE 32768    // A:128 rows + B:128 rows, 128B each
#define HSMEM  (3*HSTAGE)
#define STGN   (128*129)   // fp32 staging floats (66048 B)

template<typename TO, bool ADD, bool TRI, bool PVK, bool MIX, bool QKV, bool GLU, bool SMAX>
__global__ void __launch_bounds__(256, 2) hgemm(
    const __half* __restrict__ A, const __half* __restrict__ B, TO* __restrict__ C,
    int Kn, int Nn, long long sA, long long sB, long long sC,
    float* __restrict__ invp, __half* __restrict__ aux1, __half* __restrict__ aux2,
    const float* __restrict__ addsrc)
{
    extern __shared__ __align__(128) char sm[];
    const uint32_t sbase = smem_u32(sm);

    int bi, bj;
    if (TRI) {
        int x = blockIdx.x, i = 0;
        while ((i + 1) * (i + 2) / 2 <= x) i++;
        bi = i; bj = x - i * (i + 1) / 2;
    } else { bi = blockIdx.y; bj = blockIdx.x; }

    A += (long long)blockIdx.z * sA + (long long)(bi * 128) * Kn;
    B += (long long)blockIdx.z * sB + (long long)(bj * 128) * Kn;
    C += (long long)blockIdx.z * sC;

    const int NC = PVK ? 2 * (blockIdx.y + 1) : (Kn >> 6);

    const int tid = threadIdx.x, warp = tid >> 5, lane = tid & 31;
    const int gid = lane >> 2, tig = lane & 3;
    const int wm = (warp & 3) * 32, wn = (warp >> 2) * 64;

    const int mi = lane >> 3, ri = lane & 7;
    const int fro = (mi & 1) * 8 + ri;
    const int khalf = mi >> 1;

    float acc[2][8][4];
#pragma unroll
    for (int mt = 0; mt < 2; mt++)
#pragma unroll
        for (int nt = 0; nt < 8; nt++)
#pragma unroll
            for (int j = 0; j < 4; j++) acc[mt][nt][j] = 0.f;

    const int lr = tid >> 3;
    const int lseg = tid & 7;

    auto load = [&](int chunk) {
        if (chunk < NC) {
            const uint32_t st = sbase + (uint32_t)(chunk % 3) * HSTAGE;
            const __half* Ag = A + chunk * 64;
            const __half* Bg = B + chunk * 64;
#pragma unroll
            for (int it = 0; it < 4; it++) {
                int r = lr + it * 32;
                uint32_t off = (uint32_t)(r * 128 + ((lseg ^ (r & 7)) << 4));
                cpasync16(st + off,         Ag + (long long)r * Kn + lseg * 8);
                cpasync16(st + 16384 + off, Bg + (long long)r * Kn + lseg * 8);
            }
        }
        CP_COMMIT();
    };

    load(0);
    load(1);

    const int arow[2] = { wm + fro, wm + 16 + fro };
    const int brow[4] = { wn + fro, wn + 16 + fro, wn + 32 + fro, wn + 48 + fro };

    for (int c = 0; c < NC; c++) {
        CP_WAIT1();
        __syncthreads();
        load(c + 2);

        const uint32_t st = sbase + (uint32_t)(c % 3) * HSTAGE;
#pragma unroll
        for (int kb = 0; kb < 64; kb += 16) {
            const int ks = (kb >> 3) + khalf;
            uint32_t a[2][4], b[4][4];
#pragma unroll
            for (int mt = 0; mt < 2; mt++) {
                int r = arow[mt];
                ldmx4(a[mt], st + (uint32_t)(r * 128 + ((ks ^ (r & 7)) << 4)));
            }
#pragma unroll
            for (int np = 0; np < 4; np++) {
                int r = brow[np];
                ldmx4(b[np], st + 16384u + (uint32_t)(r * 128 + ((ks ^ (r & 7)) << 4)));
            }
#pragma unroll
            for (int mt = 0; mt < 2; mt++)
#pragma unroll
                for (int nt = 0; nt < 8; nt++)
                    mma16816(acc[mt][nt], a[mt], b[nt >> 1][nt & 1], b[nt >> 1][2 + (nt & 1)]);
        }
    }

    if constexpr (GLU) {
        __half* hr = (__half*)C;          // stride FF
#pragma unroll
        for (int mt = 0; mt < 2; mt++) {
            int row0 = bi * 128 + wm + mt * 16 + gid;
#pragma unroll
            for (int nt = 0; nt < 8; nt++) {
                int jg = bj * 64 + ((wn + nt * 8) >> 1) + tig;
                float g0 = acc[mt][nt][0], u0 = acc[mt][nt][1];
                float g1 = acc[mt][nt][2], u1 = acc[mt][nt][3];
                hr[(long long)row0 * FF + jg]       = __float2half(g0 / (1.f + __expf(-g0)) * u0);
                hr[(long long)(row0 + 8) * FF + jg] = __float2half(g1 / (1.f + __expf(-g1)) * u1);
            }
        }
        return;
    }

    if constexpr (MIX || QKV || SMAX) {
        float* stg = (float*)sm;
        __syncthreads();
#pragma unroll
        for (int mt = 0; mt < 2; mt++) {
            int rr = wm + mt * 16 + gid;
#pragma unroll
            for (int nt = 0; nt < 8; nt++) {
                int cc = wn + nt * 8 + 2 * tig;
                stg[rr * 129 + cc]           = acc[mt][nt][0];
                stg[rr * 129 + cc + 1]       = acc[mt][nt][1];
                stg[(rr + 8) * 129 + cc]     = acc[mt][nt][2];
                stg[(rr + 8) * 129 + cc + 1] = acc[mt][nt][3];
            }
        }
        __syncthreads();
    }

    if constexpr (SMAX) {
        float* stg = (float*)sm;
        float* sred = (float*)(sm + STGN * 4);    // 256 floats after staging
        const int bh = blockIdx.z;
        const int r = tid >> 1, c0 = (tid & 1) * 64;
        const int qi = bi * 128 + r;
        __half* dst = (__half*)C + (long long)qi * SS + bj * 128 + c0;
        float sum = 0.f;
#pragma unroll
        for (int k = 0; k < 64; k += 8) {
            __half ev[8];
#pragma unroll
            for (int u = 0; u < 8; u++) {
                int kj = bj * 128 + c0 + k + u;
                float e = (kj <= qi) ? __expf(stg[r * 129 + c0 + k + u] * SCALE - ESHIFT) : 0.f;
                ev[u] = __float2half(e);
                sum += e;
            }
            *(uint4*)(dst + k) = *(uint4*)ev;
        }
        sred[tid] = sum;
        __syncthreads();
        if (tid < 128)
            atomicAdd(&invp[(long long)bh * SS + bi * 128 + tid],
                      sred[2 * tid] + sred[2 * tid + 1]);
        return;
    }

    if constexpr (MIX) {
        float* stg = (float*)sm;
        const int bh = blockIdx.z;
        const int b = bh >> 4, h = bh & 15;
        __half* xo = (__half*)C;          // C = xn base (sC == 0)
        for (int i = tid; i < 128 * 128; i += 256) {
            int r = i >> 7, d = i & 127;
            int sg = bi * 128 + r;
            float iv = invp[(long long)bh * SS + sg];
            float v  = stg[r * 129 + d] * iv;
            float pv = stg[r * 129 + ((d + 127) & 127)] * iv;
            xo[((long long)(b * SS + sg)) * DD + h * DHD + d] =
                __float2half(v * (1.f + HS * pv));
        }
        return;
    }

    if constexpr (QKV) {
        float* stg = (float*)sm;
        const int htype = bj >> 4, h = bj & 15;
        const int bq = (bi * 128) >> 10;
        const int s0 = (bi * 128) & 1023;
        if (htype < 2) {
            __half* dst = (htype == 0) ? (__half*)C : aux1;   // qa : ka
            for (int i = tid; i < 128 * 64; i += 256) {
                int r = i >> 6, dd = i & 63;
                int s = s0 + r;
                float v1 = stg[r * 129 + dd];
                float v2 = stg[r * 129 + dd + 64];
                float invf = __expf(-(float)dd * (9.210340371976184f / 64.0f));
                float ang = (float)s * invf;
                float cs, sn; __sincosf(ang, &sn, &cs);
                float o1 = v1 * cs - v2 * sn;
                float o2 = v1 * sn + v2 * cs;
                long long base = (((long long)(bq * HH + h)) * SS + s) * KAUG;
                dst[base + dd]              = __float2half(o1);
                dst[base + HALF + dd]       = __float2half(o2);
                dst[base + DHD + dd]        = __float2half(SQLAM * o1 * o1);
                dst[base + DHD + HALF + dd] = __float2half(SQLAM * o2 * o2);
            }
        } else {
            const int bh = bq * HH + h;
            for (int i = tid; i < 128 * 128; i += 256) {
                int d = i >> 7, sl = i & 127;
                aux2[((long long)(bh * DHD + d)) * SS + s0 + sl] =
                    __float2half(stg[sl * 129 + d]);
            }
        }
        return;
    }

    // standard epilogue
#pragma unroll
    for (int mt = 0; mt < 2; mt++) {
        int r0 = bi * 128 + wm + mt * 16 + gid;
#pragma unroll
        for (int nt = 0; nt < 8; nt++) {
            int cc = bj * 128 + wn + nt * 8 + 2 * tig;
            TO* p0 = C + (long long)r0 * Nn + cc;
            TO* p1 = p0 + 8 * (long long)Nn;
            if constexpr (sizeof(TO) == 2) {
                *(__half2*)p0 = __floats2half2_rn(acc[mt][nt][0], acc[mt][nt][1]);
                *(__half2*)p1 = __floats2half2_rn(acc[mt][nt][2], acc[mt][nt][3]);
            } else if (ADD) {
                if (addsrc) {
                    const float* s0p = addsrc + (long long)r0 * Nn + cc;
                    const float* s1p = s0p + 8 * (long long)Nn;
                    p0[0] = s0p[0] + acc[mt][nt][0]; p0[1] = s0p[1] + acc[mt][nt][1];
                    p1[0] = s1p[0] + acc[mt][nt][2]; p1[1] = s1p[1] + acc[mt][nt][3];
                } else {
                    p0[0] += acc[mt][nt][0]; p0[1] += acc[mt][nt][1];
                    p1[0] += acc[mt][nt][2]; p1[1] += acc[mt][nt][3];
                }
            } else {
                p0[0] = acc[mt][nt][0]; p0[1] = acc[mt][nt][1];
                p1[0] = acc[mt][nt][2]; p1[1] = acc[mt][nt][3];
            }
        }
    }
}

// ---------------- RMSNorm -> fp16 (float4 loads, uint2 fp16 stores) ----------------
__global__ void rmsnorm_k(const float* __restrict__ x, const float* __restrict__ sc,
                          __half* __restrict__ o)
{
    const int row = blockIdx.x;
    const float4* xr = (const float4*)(x + (long long)row * DD);
    const float4* sc4 = (const float4*)sc;
    uint2* orw = (uint2*)(o + (long long)row * DD);
    const int tid = threadIdx.x;

    float4 v0 = xr[tid], v1 = xr[tid + 256];
    float s = v0.x*v0.x + v0.y*v0.y + v0.z*v0.z + v0.w*v0.w
            + v1.x*v1.x + v1.y*v1.y + v1.z*v1.z + v1.w*v1.w;
    __shared__ float red[256];
    red[tid] = s; __syncthreads();
    for (int t = 128; t > 0; t >>= 1) {
        if (tid < t) red[tid] += red[tid + t];
        __syncthreads();
    }
    float r = rsqrtf(red[0] * (1.0f / DD) + EPSV);
    float4 s0 = sc4[tid], s1 = sc4[tid + 256];
    float4 o0 = make_float4(v0.x*r*s0.x, v0.y*r*s0.y, v0.z*r*s0.z, v0.w*r*s0.w);
    float4 o1 = make_float4(v1.x*r*s1.x, v1.y*r*s1.y, v1.z*r*s1.z, v1.w*r*s1.w);
    orw[tid]       = f4_to_h4(o0);
    orw[tid + 256] = f4_to_h4(o1);
}

// ---------------- FFN hadamard mix (vectorized): hh[c] = hr[c]*(1+HS*hr[c-1]) ----------------
__global__ void mixf_k(const __half* __restrict__ hr, __half* __restrict__ hh)
{
    int t = blockIdx.x * 256 + threadIdx.x;       // M*F/8 threads
    int m = t >> 10;
    int c0 = (t & 1023) << 3;
    const __half* row = hr + (long long)m * FF;
    __half in[8];
    *(uint4*)in = *(const uint4*)(row + c0);
    float hprev = __half2float(row[(c0 + FF - 1) & (FF - 1)]);
    __half outv[8];
#pragma unroll
    for (int k = 0; k < 8; k++) {
        float h = __half2float(in[k]);
        outv[k] = __float2half(h * (1.f + HS * hprev));
        hprev = h;
    }
    *(uint4*)(hh + (long long)m * FF + c0) = *(uint4*)outv;
}

// ---------------- misc elementwise ----------------
__global__ void zero_k(float* __restrict__ p, int n)
{ int i = blockIdx.x * 256 + threadIdx.x; if (i < n) p[i] = 0.f; }

__global__ void recip_k(float* __restrict__ p, int n)
{ int i = blockIdx.x * 256 + threadIdx.x; if (i < n) p[i] = 1.f / p[i]; }

// fp32 -> fp16, 4 grid-strided float4s per thread (MLP=4; n4 divisible by 4*grid)
__global__ void w2h_k(__half* __restrict__ dst, const float* __restrict__ src, int n4)
{
    const int G = gridDim.x * 256;
    int i = blockIdx.x * 256 + threadIdx.x;
    float4 v0 = ((const float4*)src)[i];
    float4 v1 = ((const float4*)src)[i + G];
    float4 v2 = ((const float4*)src)[i + 2 * G];
    float4 v3 = ((const float4*)src)[i + 3 * G];
    ((uint2*)dst)[i]         = f4_to_h4(v0);
    ((uint2*)dst)[i + G]     = f4_to_h4(v1);
    ((uint2*)dst)[i + 2 * G] = f4_to_h4(v2);
    ((uint2*)dst)[i + 3 * G] = f4_to_h4(v3);
    (void)n4;
}

// gate/up interleave: dst row 2j <- Wg row j, row 2j+1 <- Wu row j (MLP=4)
__global__ void w2h_glu_k(__half* __restrict__ dst, const float* __restrict__ wg,
                          const float* __restrict__ wu, int n4)
{
    const int G = gridDim.x * 256;
    int i = blockIdx.x * 256 + threadIdx.x;
#pragma unroll
    for (int k = 0; k < 2; k++) {
        int e0 = i + 2 * k * G, e1 = e0 + G;
        float4 vg0 = ((const float4*)wg)[e0];
        float4 vu0 = ((const float4*)wu)[e0];
        float4 vg1 = ((const float4*)wg)[e1];
        float4 vu1 = ((const float4*)wu)[e1];
        int j0 = e0 >> 9, c0 = e0 & 511;
        int j1 = e1 >> 9, c1 = e1 & 511;
        ((uint2*)dst)[((long long)(2 * j0) << 9) + c0]     = f4_to_h4(vg0);
        ((uint2*)dst)[((long long)(2 * j0 + 1) << 9) + c0] = f4_to_h4(vu0);
        ((uint2*)dst)[((long long)(2 * j1) << 9) + c1]     = f4_to_h4(vg1);
        ((uint2*)dst)[((long long)(2 * j1 + 1) << 9) + c1] = f4_to_h4(vu1);
    }
    (void)n4;
}

// x2 = (1+beta)*h1 - beta*x  (float4; n4 = n/4)
__global__ void x2_k(float* __restrict__ dst, const float* __restrict__ h1,
                     const float* __restrict__ x, int n4)
{
    int i = blockIdx.x * 256 + threadIdx.x;
    if (i < n4) {
        float4 a = ((const float4*)h1)[i];
        float4 b = ((const float4*)x)[i];
        ((float4*)dst)[i] = make_float4(
            (1.f + BETA) * a.x - BETA * b.x, (1.f + BETA) * a.y - BETA * b.y,
            (1.f + BETA) * a.z - BETA * b.z, (1.f + BETA) * a.w - BETA * b.w);
    }
}

__global__ void final_k(float* __restrict__ out, const float* __restrict__ h1,
                        const float* __restrict__ h2, int n4)
{
    int i = blockIdx.x * 256 + threadIdx.x;
    if (i < n4) {
        float4 a = ((const float4*)h1)[i];
        float4 b = ((const float4*)h2)[i];
        float4 r;
        r.x = fminf(fmaxf(ALPHA * a.x + (1.f - ALPHA) * b.x, -CLIPV), CLIPV);
        r.y = fminf(fmaxf(ALPHA * a.y + (1.f - ALPHA) * b.y, -CLIPV), CLIPV);
        r.z = fminf(fmaxf(ALPHA * a.z + (1.f - ALPHA) * b.z, -CLIPV), CLIPV);
        r.w = fminf(fmaxf(ALPHA * a.w + (1.f - ALPHA) * b.w, -CLIPV), CLIPV);
        ((float4*)out)[i] = r;
    }
}

// ---------------- host orchestration ----------------
static void run_pass(const __half* wqkv, const __half* wo, const __half* wgu, const __half* wd,
                     const float* na, const float* nb,
                     const float* nsrc, const float* addsrc,
                     float* cur, __half* xn,
                     __half* qa, __half* ka, __half* vt, float* inv,
                     __half* ph, __half* hr, __half* hh)
{
    const int nMF = MM * FF, nInv = BB * HH * SS;

    rmsnorm_k<<<MM, 256>>>(nsrc, na, xn);

    // fused QKV + RoPE/augment + V-transpose: writes qa, ka, vt directly
    hgemm<__half,false,false,false,false,true,false,false><<<dim3(48, MM/128, 1), 256, HSMEM>>>(
        xn, wqkv, qa, DD, 3*DD, 0, 0, 0, nullptr, ka, vt, nullptr);

    // causal scores + fused shifted-exp softmax epilogue -> ph + row sums
    zero_k<<<(nInv+255)/256, 256>>>(inv, nInv);
    hgemm<__half,false,true,false,false,false,false,true><<<dim3(36, 1, BB*HH), 256, HSMEM>>>(
        qa, ka, ph, KAUG, SS,
        (long long)SS*KAUG, (long long)SS*KAUG, (long long)SS*SS, inv, nullptr, nullptr, nullptr);
    recip_k<<<(nInv+255)/256, 256>>>(inv, nInv);

    // PV with causal K truncation + fused normalize/mix/transpose epilogue -> xn
    hgemm<__half,false,false,true,true,false,false,false><<<dim3(1, SS/128, BB*HH), 256, HSMEM>>>(
        ph, vt, xn, SS, DHD,
        (long long)SS*SS, (long long)SS*DHD, 0, inv, nullptr, nullptr, nullptr);

    hgemm<float,true,false,false,false,false,false,false><<<dim3(DD/128, MM/128, 1), 256, HSMEM>>>(
        xn, wo, cur, DD, DD, 0, 0, 0, nullptr, nullptr, nullptr, addsrc);

    rmsnorm_k<<<MM, 256>>>(cur, nb, xn);
    // fused gate|up (interleaved weights) + silu*up epilogue -> hr [M,F]
    hgemm<__half,false,false,false,false,false,true,false><<<dim3(2*FF/128, MM/128, 1), 256, HSMEM>>>(
        xn, wgu, hr, DD, 2*FF, 0, 0, 0, nullptr, nullptr, nullptr, nullptr);
    mixf_k<<<nMF/8/256, 256>>>(hr, hh);
    hgemm<float,true,false,false,false,false,false,false><<<dim3(DD/128, MM/128, 1), 256, HSMEM>>>(
        hh, wd, cur, FF, DD, 0, 0, 0, nullptr, nullptr, nullptr, nullptr);
}

extern "C" void kernel_launch(void* const* d_in, const int* in_sizes, int n_in,
                              void* d_out, int out_size)
{
    (void)in_sizes; (void)n_in; (void)out_size;
    const float* x   = (const float*)d_in[0];
    const float* Wq0 = (const float*)d_in[1];
    const float* Wk0 = (const float*)d_in[2];
    const float* Wv0 = (const float*)d_in[3];
    const float* Wo0 = (const float*)d_in[4];
    // d_in[5] = gate_w: unused (rotate_half invariance => o2 == o1)
    const float* n1 = (const float*)d_in[6];
    const float* n2 = (const float*)d_in[7];
    const float* n3 = (const float*)d_in[8];
    const float* n4 = (const float*)d_in[9];
    const float* Wg0 = (const float*)d_in[10];
    const float* Wu0 = (const float*)d_in[11];
    const float* Wd0 = (const float*)d_in[12];
    float* out = (float*)d_out;

    cudaFuncSetAttribute(hgemm<__half,false,false,false,false,true,false,false>, cudaFuncAttributeMaxDynamicSharedMemorySize, HSMEM);
    cudaFuncSetAttribute(hgemm<float,true,false,false,false,false,false,false>,  cudaFuncAttributeMaxDynamicSharedMemorySize, HSMEM);
    cudaFuncSetAttribute(hgemm<__half,false,true,false,false,false,false,true>,  cudaFuncAttributeMaxDynamicSharedMemorySize, HSMEM);
    cudaFuncSetAttribute(hgemm<__half,false,false,true,true,false,false,false>,  cudaFuncAttributeMaxDynamicSharedMemorySize, HSMEM);
    cudaFuncSetAttribute(hgemm<__half,false,false,false,false,false,true,false>, cudaFuncAttributeMaxDynamicSharedMemorySize, HSMEM);

    __half *xn, *qa, *ka, *vt, *ph, *hr, *hh, *wqkv, *wo, *wgu, *wd;
    float *cur, *x2, *inv;
    cudaGetSymbolAddress((void**)&xn,  g_xn);
    cudaGetSymbolAddress((void**)&cur, g_cur);
    cudaGetSymbolAddress((void**)&x2,  g_x2);
    cudaGetSymbolAddress((void**)&qa,  g_qa);
    cudaGetSymbolAddress((void**)&ka,  g_ka);
    cudaGetSymbolAddress((void**)&vt,  g_vt);
    cudaGetSymbolAddress((void**)&inv, g_inv);
    cudaGetSymbolAddress((void**)&ph,  g_ph);
    cudaGetSymbolAddress((void**)&hr,  g_hr);
    cudaGetSymbolAddress((void**)&hh,  g_hh);
    cudaGetSymbolAddress((void**)&wqkv,g_wqkv);
    cudaGetSymbolAddress((void**)&wo,  g_wo);
    cudaGetSymbolAddress((void**)&wgu, g_wgu);
    cudaGetSymbolAddress((void**)&wd,  g_wd);

    const int nMD = MM * DD;

    // weights -> fp16 (qkv stacked; gate/up row-interleaved); MLP=4 grid-strided
    w2h_k<<<DD*DD/4/1024, 256>>>(wqkv,           Wq0, DD*DD/4);
    w2h_k<<<DD*DD/4/1024, 256>>>(wqkv + DD*DD,   Wk0, DD*DD/4);
    w2h_k<<<DD*DD/4/1024, 256>>>(wqkv + 2*DD*DD, Wv0, DD*DD/4);
    w2h_k<<<DD*DD/4/1024, 256>>>(wo,             Wo0, DD*DD/4);
    w2h_glu_k<<<FF*DD/4/1024, 256>>>(wgu, Wg0, Wu0, FF*DD/4);
    w2h_k<<<FF*DD/4/1024, 256>>>(wd,             Wd0, FF*DD/4);

    // pass 1: rmsnorm reads x; Wo epilogue initializes cur = x + attn (no copy)
    run_pass(wqkv, wo, wgu, wd, n1, n2, x, x,
             cur, xn, qa, ka, vt, inv, ph, hr, hh);

    // x2 = h1 + beta*(h1 - x)
    x2_k<<<(nMD/4+255)/256, 256>>>(x2, cur, x, nMD/4);

    // pass 2: rmsnorm reads x2; Wo epilogue accumulates into x2
    run_pass(wqkv, wo, wgu, wd, n3, n4, x2, nullptr,
             x2, xn, qa, ka, vt, inv, ph, hr, hh);

    // out = clip(alpha*h1 + (1-alpha)*h2)
    final_k<<<(nMD/4+255)/256, 256>>>(out, cur, x2, nMD/4);
}

// round 16
// speedup vs baseline: 1.1263x; 1.0046x over previous
#include <cuda_runtime.h>
#include <cuda_fp16.h>
#include <math.h>
#include <stdint.h>

// ---------------- problem constants ----------------
#define BB   2
#define SS   1024
#define DD   2048
#define HH   16
#define FF   8192
#define DHD  128
#define HALF 64
#define MM   (BB*SS)          // 2048 rows
#define KAUG (2*DHD)          // 256 augmented K dim

#define HS    0.05f
#define BETA  0.3f
#define ALPHA 0.5f
#define CLIPV 10.0f
#define EPSV  1e-6f
#define SCALE 0.08838834764831845f   // 1/sqrt(128)
#define SQLAM 0.31622776601683794f   // sqrt(0.1)
#define ESHIFT 4.0f                  // fixed softmax shift (cancels in normalization)

// ---------------- static device scratch ----------------
static __device__ __align__(128) __half g_xn  [MM*DD];          // rmsnorm/mix out (GEMM A)
static __device__ __align__(128) float  g_cur [MM*DD];          // pass-1 residual state (= h1)
static __device__ __align__(128) float  g_x2  [MM*DD];          // pass-2 residual state
static __device__ __align__(128) __half g_qa  [BB*HH*SS*KAUG];
static __device__ __align__(128) __half g_ka  [BB*HH*SS*KAUG];
static __device__ __align__(128) __half g_vt  [BB*HH*DHD*SS];   // per-head [DHD, S]
static __device__ __align__(128) float  g_inv [BB*HH*SS];       // row sums -> 1/sum
static __device__ __align__(128) __half g_ph  [(long long)BB*HH*SS*SS];  // unnorm probs fp16
static __device__ __align__(128) __half g_hr  [MM*FF];          // FFN silu(g)*u (unmixed)
static __device__ __align__(128) __half g_hh  [MM*FF];          // FFN hidden mixed (GEMM A)
// fp16 weights
static __device__ __align__(128) __half g_wqkv[3*DD*DD];
static __device__ __align__(128) __half g_wo  [DD*DD];
static __device__ __align__(128) __half g_wgu [2*FF*DD];        // interleaved (gate_j, up_j) rows
static __device__ __align__(128) __half g_wd  [DD*FF];

// ---------------- helpers ----------------
__device__ __forceinline__ uint32_t smem_u32(const void* p) {
    uint32_t a;
    asm("{ .reg .u64 t; cvta.to.shared.u64 t, %1; cvt.u32.u64 %0, t; }" : "=r"(a) : "l"(p));
    return a;
}
__device__ __forceinline__ void cpasync16(uint32_t dst, const void* src) {
    asm volatile("cp.async.cg.shared.global [%0], [%1], 16;" :: "r"(dst), "l"(src));
}
#define CP_COMMIT()  asm volatile("cp.async.commit_group;" ::: "memory")
#define CP_WAIT1()   asm volatile("cp.async.wait_group 1;" ::: "memory")

__device__ __forceinline__ void ldmx4(uint32_t* r, uint32_t addr) {
    asm volatile("ldmatrix.sync.aligned.m8n8.x4.shared.b16 {%0,%1,%2,%3}, [%4];"
        : "=r"(r[0]), "=r"(r[1]), "=r"(r[2]), "=r"(r[3]) : "r"(addr));
}
__device__ __forceinline__ void mma16816(float* c, const uint32_t* a, uint32_t b0, uint32_t b1) {
    asm volatile("mma.sync.aligned.m16n8k16.row.col.f32.f16.f16.f32 "
        "{%0,%1,%2,%3}, {%4,%5,%6,%7}, {%8,%9}, {%0,%1,%2,%3};"
        : "+f"(c[0]), "+f"(c[1]), "+f"(c[2]), "+f"(c[3])
        : "r"(a[0]), "r"(a[1]), "r"(a[2]), "r"(a[3]), "r"(b0), "r"(b1));
}
__device__ __forceinline__ uint2 f4_to_h4(float4 v) {
    __half2 lo = __floats2half2_rn(v.x, v.y);
    __half2 hi = __floats2half2_rn(v.z, v.w);
    return make_uint2(*(uint32_t*)&lo, *(uint32_t*)&hi);
}

// ---------------- fp16 tensor-core GEMM with fused epilogues ----------------
// C[M,N](TO) = A[M,K](f16) * B[N,K](f16)^T
// ADD (TO=float): C += acc, or C = addsrc + acc when addsrc != nullptr.
// CTA tile 128x128, chunk = 64 halves (128B rows), 3 smem slots, single-barrier
// mainloop, 2 CTA/SM.
// TRI: blockIdx.x enumerates lower-triangle 128x128 blocks (causal scores).
// PVK: K limited to (blockIdx.y+1)*128 halves (causal PV).
// MIX: PV epilogue — normalize by inv[], hadamard-mix along d, transpose-write fp16 xn.
// QKV: RoPE+augment epilogue for q/k heads (C=qa / aux1=ka), v transpose into aux2=vt.
// GLU: interleaved gate/up weights; epilogue writes silu(g)*u fp16 [M,F].
// SMAX: scores epilogue — e = exp(acc*SCALE - ESHIFT) with causal mask, write
//       fp16 ph directly, atomicAdd per-row partial sums into invp (as sums).
#define HSTAGE 32768    // A:128 rows + B:128 rows, 128B each
#define HSMEM  (3*HSTAGE)
#define STGN   (128*129)   // fp32 staging floats (66048 B)

template<typename TO, bool ADD, bool TRI, bool PVK, bool MIX, bool QKV, bool GLU, bool SMAX>
__global__ void __launch_bounds__(256, 2) hgemm(
    const __half* __restrict__ A, const __half* __restrict__ B, TO* __restrict__ C,
    int Kn, int Nn, long long sA, long long sB, long long sC,
    float* __restrict__ invp, __half* __restrict__ aux1, __half* __restrict__ aux2,
    const float* __restrict__ addsrc)
{
    extern __shared__ __align__(128) char sm[];
    const uint32_t sbase = smem_u32(sm);

    int bi, bj;
    if (TRI) {
        int x = blockIdx.x, i = 0;
        while ((i + 1) * (i + 2) / 2 <= x) i++;
        bi = i; bj = x - i * (i + 1) / 2;
    } else { bi = blockIdx.y; bj = blockIdx.x; }

    A += (long long)blockIdx.z * sA + (long long)(bi * 128) * Kn;
    B += (long long)blockIdx.z * sB + (long long)(bj * 128) * Kn;
    C += (long long)blockIdx.z * sC;

    const int NC = PVK ? 2 * (blockIdx.y + 1) : (Kn >> 6);

    const int tid = threadIdx.x, warp = tid >> 5, lane = tid & 31;
    const int gid = lane >> 2, tig = lane & 3;
    const int wm = (warp & 3) * 32, wn = (warp >> 2) * 64;

    const int mi = lane >> 3, ri = lane & 7;
    const int fro = (mi & 1) * 8 + ri;
    const int khalf = mi >> 1;

    float acc[2][8][4];
#pragma unroll
    for (int mt = 0; mt < 2; mt++)
#pragma unroll
        for (int nt = 0; nt < 8; nt++)
#pragma unroll
            for (int j = 0; j < 4; j++) acc[mt][nt][j] = 0.f;

    const int lr = tid >> 3;
    const int lseg = tid & 7;

    auto load = [&](int chunk) {
        if (chunk < NC) {
            const uint32_t st = sbase + (uint32_t)(chunk % 3) * HSTAGE;
            const __half* Ag = A + chunk * 64;
            const __half* Bg = B + chunk * 64;
#pragma unroll
            for (int it = 0; it < 4; it++) {
                int r = lr + it * 32;
                uint32_t off = (uint32_t)(r * 128 + ((lseg ^ (r & 7)) << 4));
                cpasync16(st + off,         Ag + (long long)r * Kn + lseg * 8);
                cpasync16(st + 16384 + off, Bg + (long long)r * Kn + lseg * 8);
            }
        }
        CP_COMMIT();
    };

    load(0);
    load(1);

    const int arow[2] = { wm + fro, wm + 16 + fro };
    const int brow[4] = { wn + fro, wn + 16 + fro, wn + 32 + fro, wn + 48 + fro };

    for (int c = 0; c < NC; c++) {
        CP_WAIT1();
        __syncthreads();
        load(c + 2);

        const uint32_t st = sbase + (uint32_t)(c % 3) * HSTAGE;
#pragma unroll
        for (int kb = 0; kb < 64; kb += 16) {
            const int ks = (kb >> 3) + khalf;
            uint32_t a[2][4], b[4][4];
#pragma unroll
            for (int mt = 0; mt < 2; mt++) {
                int r = arow[mt];
                ldmx4(a[mt], st + (uint32_t)(r * 128 + ((ks ^ (r & 7)) << 4)));
            }
#pragma unroll
            for (int np = 0; np < 4; np++) {
                int r = brow[np];
                ldmx4(b[np], st + 16384u + (uint32_t)(r * 128 + ((ks ^ (r & 7)) << 4)));
            }
#pragma unroll
            for (int mt = 0; mt < 2; mt++)
#pragma unroll
                for (int nt = 0; nt < 8; nt++)
                    mma16816(acc[mt][nt], a[mt], b[nt >> 1][nt & 1], b[nt >> 1][2 + (nt & 1)]);
        }
    }

    if constexpr (GLU) {
        __half* hr = (__half*)C;          // stride FF
#pragma unroll
        for (int mt = 0; mt < 2; mt++) {
            int row0 = bi * 128 + wm + mt * 16 + gid;
#pragma unroll
            for (int nt = 0; nt < 8; nt++) {
                int jg = bj * 64 + ((wn + nt * 8) >> 1) + tig;
                float g0 = acc[mt][nt][0], u0 = acc[mt][nt][1];
                float g1 = acc[mt][nt][2], u1 = acc[mt][nt][3];
                hr[(long long)row0 * FF + jg]       = __float2half(g0 / (1.f + __expf(-g0)) * u0);
                hr[(long long)(row0 + 8) * FF + jg] = __float2half(g1 / (1.f + __expf(-g1)) * u1);
            }
        }
        return;
    }

    if constexpr (MIX || QKV || SMAX) {
        float* stg = (float*)sm;
        __syncthreads();
#pragma unroll
        for (int mt = 0; mt < 2; mt++) {
            int rr = wm + mt * 16 + gid;
#pragma unroll
            for (int nt = 0; nt < 8; nt++) {
                int cc = wn + nt * 8 + 2 * tig;
                stg[rr * 129 + cc]           = acc[mt][nt][0];
                stg[rr * 129 + cc + 1]       = acc[mt][nt][1];
                stg[(rr + 8) * 129 + cc]     = acc[mt][nt][2];
                stg[(rr + 8) * 129 + cc + 1] = acc[mt][nt][3];
            }
        }
        __syncthreads();
    }

    if constexpr (SMAX) {
        float* stg = (float*)sm;
        float* sred = (float*)(sm + STGN * 4);    // 256 floats after staging
        const int bh = blockIdx.z;
        const int r = tid >> 1, c0 = (tid & 1) * 64;
        const int qi = bi * 128 + r;
        __half* dst = (__half*)C + (long long)qi * SS + bj * 128 + c0;
        float sum = 0.f;
#pragma unroll
        for (int k = 0; k < 64; k += 8) {
            __half ev[8];
#pragma unroll
            for (int u = 0; u < 8; u++) {
                int kj = bj * 128 + c0 + k + u;
                float e = (kj <= qi) ? __expf(stg[r * 129 + c0 + k + u] * SCALE - ESHIFT) : 0.f;
                ev[u] = __float2half(e);
                sum += e;
            }
            *(uint4*)(dst + k) = *(uint4*)ev;
        }
        sred[tid] = sum;
        __syncthreads();
        if (tid < 128)
            atomicAdd(&invp[(long long)bh * SS + bi * 128 + tid],
                      sred[2 * tid] + sred[2 * tid + 1]);
        return;
    }

    if constexpr (MIX) {
        float* stg = (float*)sm;
        const int bh = blockIdx.z;
        const int b = bh >> 4, h = bh & 15;
        __half* xo = (__half*)C;          // C = xn base (sC == 0)
        for (int i = tid; i < 128 * 128; i += 256) {
            int r = i >> 7, d = i & 127;
            int sg = bi * 128 + r;
            float iv = invp[(long long)bh * SS + sg];
            float v  = stg[r * 129 + d] * iv;
            float pv = stg[r * 129 + ((d + 127) & 127)] * iv;
            xo[((long long)(b * SS + sg)) * DD + h * DHD + d] =
                __float2half(v * (1.f + HS * pv));
        }
        return;
    }

    if constexpr (QKV) {
        float* stg = (float*)sm;
        const int htype = bj >> 4, h = bj & 15;
        const int bq = (bi * 128) >> 10;
        const int s0 = (bi * 128) & 1023;
        if (htype < 2) {
            __half* dst = (htype == 0) ? (__half*)C : aux1;   // qa : ka
            for (int i = tid; i < 128 * 64; i += 256) {
                int r = i >> 6, dd = i & 63;
                int s = s0 + r;
                float v1 = stg[r * 129 + dd];
                float v2 = stg[r * 129 + dd + 64];
                float invf = __expf(-(float)dd * (9.210340371976184f / 64.0f));
                float ang = (float)s * invf;
                float cs, sn; __sincosf(ang, &sn, &cs);
                float o1 = v1 * cs - v2 * sn;
                float o2 = v1 * sn + v2 * cs;
                long long base = (((long long)(bq * HH + h)) * SS + s) * KAUG;
                dst[base + dd]              = __float2half(o1);
                dst[base + HALF + dd]       = __float2half(o2);
                dst[base + DHD + dd]        = __float2half(SQLAM * o1 * o1);
                dst[base + DHD + HALF + dd] = __float2half(SQLAM * o2 * o2);
            }
        } else {
            const int bh = bq * HH + h;
            for (int i = tid; i < 128 * 128; i += 256) {
                int d = i >> 7, sl = i & 127;
                aux2[((long long)(bh * DHD + d)) * SS + s0 + sl] =
                    __float2half(stg[sl * 129 + d]);
            }
        }
        return;
    }

    // standard epilogue
#pragma unroll
    for (int mt = 0; mt < 2; mt++) {
        int r0 = bi * 128 + wm + mt * 16 + gid;
#pragma unroll
        for (int nt = 0; nt < 8; nt++) {
            int cc = bj * 128 + wn + nt * 8 + 2 * tig;
            TO* p0 = C + (long long)r0 * Nn + cc;
            TO* p1 = p0 + 8 * (long long)Nn;
            if constexpr (sizeof(TO) == 2) {
                *(__half2*)p0 = __floats2half2_rn(acc[mt][nt][0], acc[mt][nt][1]);
                *(__half2*)p1 = __floats2half2_rn(acc[mt][nt][2], acc[mt][nt][3]);
            } else if (ADD) {
                if (addsrc) {
                    const float* s0p = addsrc + (long long)r0 * Nn + cc;
                    const float* s1p = s0p + 8 * (long long)Nn;
                    p0[0] = s0p[0] + acc[mt][nt][0]; p0[1] = s0p[1] + acc[mt][nt][1];
                    p1[0] = s1p[0] + acc[mt][nt][2]; p1[1] = s1p[1] + acc[mt][nt][3];
                } else {
                    p0[0] += acc[mt][nt][0]; p0[1] += acc[mt][nt][1];
                    p1[0] += acc[mt][nt][2]; p1[1] += acc[mt][nt][3];
                }
            } else {
                p0[0] = acc[mt][nt][0]; p0[1] = acc[mt][nt][1];
                p1[0] = acc[mt][nt][2]; p1[1] = acc[mt][nt][3];
            }
        }
    }
}

// ---------------- RMSNorm -> fp16 (float4 loads, uint2 fp16 stores) ----------------
__global__ void rmsnorm_k(const float* __restrict__ x, const float* __restrict__ sc,
                          __half* __restrict__ o)
{
    const int row = blockIdx.x;
    const float4* xr = (const float4*)(x + (long long)row * DD);
    const float4* sc4 = (const float4*)sc;
    uint2* orw = (uint2*)(o + (long long)row * DD);
    const int tid = threadIdx.x;

    float4 v0 = xr[tid], v1 = xr[tid + 256];
    float s = v0.x*v0.x + v0.y*v0.y + v0.z*v0.z + v0.w*v0.w
            + v1.x*v1.x + v1.y*v1.y + v1.z*v1.z + v1.w*v1.w;
    __shared__ float red[256];
    red[tid] = s; __syncthreads();
    for (int t = 128; t > 0; t >>= 1) {
        if (tid < t) red[tid] += red[tid + t];
        __syncthreads();
    }
    float r = rsqrtf(red[0] * (1.0f / DD) + EPSV);
    float4 s0 = sc4[tid], s1 = sc4[tid + 256];
    float4 o0 = make_float4(v0.x*r*s0.x, v0.y*r*s0.y, v0.z*r*s0.z, v0.w*r*s0.w);
    float4 o1 = make_float4(v1.x*r*s1.x, v1.y*r*s1.y, v1.z*r*s1.z, v1.w*r*s1.w);
    orw[tid]       = f4_to_h4(o0);
    orw[tid + 256] = f4_to_h4(o1);
}

// ---------------- FFN hadamard mix (vectorized): hh[c] = hr[c]*(1+HS*hr[c-1]) ----------------
__global__ void mixf_k(const __half* __restrict__ hr, __half* __restrict__ hh)
{
    int t = blockIdx.x * 256 + threadIdx.x;       // M*F/8 threads
    int m = t >> 10;
    int c0 = (t & 1023) << 3;
    const __half* row = hr + (long long)m * FF;
    __half in[8];
    *(uint4*)in = *(const uint4*)(row + c0);
    float hprev = __half2float(row[(c0 + FF - 1) & (FF - 1)]);
    __half outv[8];
#pragma unroll
    for (int k = 0; k < 8; k++) {
        float h = __half2float(in[k]);
        outv[k] = __float2half(h * (1.f + HS * hprev));
        hprev = h;
    }
    *(uint4*)(hh + (long long)m * FF + c0) = *(uint4*)outv;
}

// ---------------- misc elementwise ----------------
__global__ void zero_k(float* __restrict__ p, int n)
{ int i = blockIdx.x * 256 + threadIdx.x; if (i < n) p[i] = 0.f; }

__global__ void recip_k(float* __restrict__ p, int n)
{ int i = blockIdx.x * 256 + threadIdx.x; if (i < n) p[i] = 1.f / p[i]; }

// ---------------- unified weight conversion (all 7 fp32 matrices -> fp16) ----------------
// Flat float4-unit index space:
//   [0,      4*NQ)   : wq, wk, wv -> g_wqkv segments; wo -> g_wo   (NQ = DD*DD/4 = 2^20)
//   [4NQ,    4NQ+NW) : wd -> g_wd                                   (NW = FF*DD/4 = 2^22)
//   [4NQ+NW, 4NQ+3NW): wg (even rows) / wu (odd rows) -> g_wgu interleaved
// Total = 4*NQ + 3*NW = 2^22 + 3*2^22 = 16M units. Grid-strided, 4 units/thread.
#define NQ4 (DD*DD/4)
#define NW4 (FF*DD/4)
#define WCONV_TOTAL (4*NQ4 + 3*NW4)

__global__ void __launch_bounds__(256) wconv_k(
    const float4* __restrict__ wq, const float4* __restrict__ wk,
    const float4* __restrict__ wv, const float4* __restrict__ wo,
    const float4* __restrict__ wg, const float4* __restrict__ wu,
    const float4* __restrict__ wdd,
    uint2* __restrict__ dqkv, uint2* __restrict__ dwo,
    uint2* __restrict__ dgu,  uint2* __restrict__ dwd)
{
    const int G = gridDim.x * 256;
    int i = blockIdx.x * 256 + threadIdx.x;
#pragma unroll
    for (int it = 0; it < 4; it++, i += G) {
        if (i < 4 * NQ4) {
            int seg = i >> 20, off = i & (NQ4 - 1);
            const float4* s = (seg == 0) ? wq : (seg == 1) ? wk : (seg == 2) ? wv : wo;
            uint2 h = f4_to_h4(__ldcs(s + off));
            if (seg < 3) dqkv[(long long)seg * NQ4 + off] = h;
            else         dwo[off] = h;
        } else if (i < 4 * NQ4 + NW4) {
            int off = i - 4 * NQ4;
            dwd[off] = f4_to_h4(__ldcs(wdd + off));
        } else {
            int e = i - 4 * NQ4 - NW4;          // 0 .. 2*NW4
            int isU = e >= NW4;
            int off = isU ? e - NW4 : e;
            const float4* s = isU ? wu : wg;
            int j = off >> 9, c = off & 511;    // DD/4 = 512 float4 per row
            dgu[((long long)(2 * j + isU) << 9) + c] = f4_to_h4(__ldcs(s + off));
        }
    }
}

// x2 = (1+beta)*h1 - beta*x  (float4; n4 = n/4)
__global__ void x2_k(float* __restrict__ dst, const float* __restrict__ h1,
                     const float* __restrict__ x, int n4)
{
    int i = blockIdx.x * 256 + threadIdx.x;
    if (i < n4) {
        float4 a = ((const float4*)h1)[i];
        float4 b = ((const float4*)x)[i];
        ((float4*)dst)[i] = make_float4(
            (1.f + BETA) * a.x - BETA * b.x, (1.f + BETA) * a.y - BETA * b.y,
            (1.f + BETA) * a.z - BETA * b.z, (1.f + BETA) * a.w - BETA * b.w);
    }
}

__global__ void final_k(float* __restrict__ out, const float* __restrict__ h1,
                        const float* __restrict__ h2, int n4)
{
    int i = blockIdx.x * 256 + threadIdx.x;
    if (i < n4) {
        float4 a = ((const float4*)h1)[i];
        float4 b = ((const float4*)h2)[i];
        float4 r;
        r.x = fminf(fmaxf(ALPHA * a.x + (1.f - ALPHA) * b.x, -CLIPV), CLIPV);
        r.y = fminf(fmaxf(ALPHA * a.y + (1.f - ALPHA) * b.y, -CLIPV), CLIPV);
        r.z = fminf(fmaxf(ALPHA * a.z + (1.f - ALPHA) * b.z, -CLIPV), CLIPV);
        r.w = fminf(fmaxf(ALPHA * a.w + (1.f - ALPHA) * b.w, -CLIPV), CLIPV);
        ((float4*)out)[i] = r;
    }
}

// ---------------- host orchestration ----------------
static void run_pass(const __half* wqkv, const __half* wo, const __half* wgu, const __half* wd,
                     const float* na, const float* nb,
                     const float* nsrc, const float* addsrc,
                     float* cur, __half* xn,
                     __half* qa, __half* ka, __half* vt, float* inv,
                     __half* ph, __half* hr, __half* hh)
{
    const int nMF = MM * FF, nInv = BB * HH * SS;

    rmsnorm_k<<<MM, 256>>>(nsrc, na, xn);

    // fused QKV + RoPE/augment + V-transpose: writes qa, ka, vt directly
    hgemm<__half,false,false,false,false,true,false,false><<<dim3(48, MM/128, 1), 256, HSMEM>>>(
        xn, wqkv, qa, DD, 3*DD, 0, 0, 0, nullptr, ka, vt, nullptr);

    // causal scores + fused shifted-exp softmax epilogue -> ph + row sums
    zero_k<<<(nInv+255)/256, 256>>>(inv, nInv);
    hgemm<__half,false,true,false,false,false,false,true><<<dim3(36, 1, BB*HH), 256, HSMEM>>>(
        qa, ka, ph, KAUG, SS,
        (long long)SS*KAUG, (long long)SS*KAUG, (long long)SS*SS, inv, nullptr, nullptr, nullptr);
    recip_k<<<(nInv+255)/256, 256>>>(inv, nInv);

    // PV with causal K truncation + fused normalize/mix/transpose epilogue -> xn
    hgemm<__half,false,false,true,true,false,false,false><<<dim3(1, SS/128, BB*HH), 256, HSMEM>>>(
        ph, vt, xn, SS, DHD,
        (long long)SS*SS, (long long)SS*DHD, 0, inv, nullptr, nullptr, nullptr);

    hgemm<float,true,false,false,false,false,false,false><<<dim3(DD/128, MM/128, 1), 256, HSMEM>>>(
        xn, wo, cur, DD, DD, 0, 0, 0, nullptr, nullptr, nullptr, addsrc);

    rmsnorm_k<<<MM, 256>>>(cur, nb, xn);
    // fused gate|up (interleaved weights) + silu*up epilogue -> hr [M,F]
    hgemm<__half,false,false,false,false,false,true,false><<<dim3(2*FF/128, MM/128, 1), 256, HSMEM>>>(
        xn, wgu, hr, DD, 2*FF, 0, 0, 0, nullptr, nullptr, nullptr, nullptr);
    mixf_k<<<nMF/8/256, 256>>>(hr, hh);
    hgemm<float,true,false,false,false,false,false,false><<<dim3(DD/128, MM/128, 1), 256, HSMEM>>>(
        hh, wd, cur, FF, DD, 0, 0, 0, nullptr, nullptr, nullptr, nullptr);
}

extern "C" void kernel_launch(void* const* d_in, const int* in_sizes, int n_in,
                              void* d_out, int out_size)
{
    (void)in_sizes; (void)n_in; (void)out_size;
    const float* x   = (const float*)d_in[0];
    const float* Wq0 = (const float*)d_in[1];
    const float* Wk0 = (const float*)d_in[2];
    const float* Wv0 = (const float*)d_in[3];
    const float* Wo0 = (const float*)d_in[4];
    // d_in[5] = gate_w: unused (rotate_half invariance => o2 == o1)
    const float* n1 = (const float*)d_in[6];
    const float* n2 = (const float*)d_in[7];
    const float* n3 = (const float*)d_in[8];
    const float* n4 = (const float*)d_in[9];
    const float* Wg0 = (const float*)d_in[10];
    const float* Wu0 = (const float*)d_in[11];
    const float* Wd0 = (const float*)d_in[12];
    float* out = (float*)d_out;

    cudaFuncSetAttribute(hgemm<__half,false,false,false,false,true,false,false>, cudaFuncAttributeMaxDynamicSharedMemorySize, HSMEM);
    cudaFuncSetAttribute(hgemm<float,true,false,false,false,false,false,false>,  cudaFuncAttributeMaxDynamicSharedMemorySize, HSMEM);
    cudaFuncSetAttribute(hgemm<__half,false,true,false,false,false,false,true>,  cudaFuncAttributeMaxDynamicSharedMemorySize, HSMEM);
    cudaFuncSetAttribute(hgemm<__half,false,false,true,true,false,false,false>,  cudaFuncAttributeMaxDynamicSharedMemorySize, HSMEM);
    cudaFuncSetAttribute(hgemm<__half,false,false,false,false,false,true,false>, cudaFuncAttributeMaxDynamicSharedMemorySize, HSMEM);

    __half *xn, *qa, *ka, *vt, *ph, *hr, *hh, *wqkv, *wo, *wgu, *wd;
    float *cur, *x2, *inv;
    cudaGetSymbolAddress((void**)&xn,  g_xn);
    cudaGetSymbolAddress((void**)&cur, g_cur);
    cudaGetSymbolAddress((void**)&x2,  g_x2);
    cudaGetSymbolAddress((void**)&qa,  g_qa);
    cudaGetSymbolAddress((void**)&ka,  g_ka);
    cudaGetSymbolAddress((void**)&vt,  g_vt);
    cudaGetSymbolAddress((void**)&inv, g_inv);
    cudaGetSymbolAddress((void**)&ph,  g_ph);
    cudaGetSymbolAddress((void**)&hr,  g_hr);
    cudaGetSymbolAddress((void**)&hh,  g_hh);
    cudaGetSymbolAddress((void**)&wqkv,g_wqkv);
    cudaGetSymbolAddress((void**)&wo,  g_wo);
    cudaGetSymbolAddress((void**)&wgu, g_wgu);
    cudaGetSymbolAddress((void**)&wd,  g_wd);

    const int nMD = MM * DD;

    // unified weight conversion: one kernel, 16M float4 units, 4/thread
    wconv_k<<<WCONV_TOTAL/1024, 256>>>(
        (const float4*)Wq0, (const float4*)Wk0, (const float4*)Wv0, (const float4*)Wo0,
        (const float4*)Wg0, (const float4*)Wu0, (const float4*)Wd0,
        (uint2*)wqkv, (uint2*)wo, (uint2*)wgu, (uint2*)wd);

    // pass 1: rmsnorm reads x; Wo epilogue initializes cur = x + attn (no copy)
    run_pass(wqkv, wo, wgu, wd, n1, n2, x, x,
             cur, xn, qa, ka, vt, inv, ph, hr, hh);

    // x2 = h1 + beta*(h1 - x)
    x2_k<<<(nMD/4+255)/256, 256>>>(x2, cur, x, nMD/4);

    // pass 2: rmsnorm reads x2; Wo epilogue accumulates into x2
    run_pass(wqkv, wo, wgu, wd, n3, n4, x2, nullptr,
             x2, xn, qa, ka, vt, inv, ph, hr, hh);

    // out = clip(alpha*h1 + (1-alpha)*h2)
    final_k<<<(nMD/4+255)/256, 256>>>(out, cur, x2, nMD/4);
}

// round 17
// speedup vs baseline: 1.1361x; 1.0087x over previous
#include <cuda_runtime.h>
#include <cuda_fp16.h>
#include <math.h>
#include <stdint.h>

// ---------------- problem constants ----------------
#define BB   2
#define SS   1024
#define DD   2048
#define HH   16
#define FF   8192
#define DHD  128
#define HALF 64
#define MM   (BB*SS)          // 2048 rows
#define KAUG (2*DHD)          // 256 augmented K dim

#define HS    0.05f
#define BETA  0.3f
#define ALPHA 0.5f
#define CLIPV 10.0f
#define EPSV  1e-6f
#define SCALE 0.08838834764831845f   // 1/sqrt(128)
#define SQLAM 0.31622776601683794f   // sqrt(0.1)
#define ESHIFT 4.0f                  // fixed softmax shift (cancels in normalization)

// ---------------- static device scratch ----------------
static __device__ __align__(128) __half g_xn  [MM*DD];          // rmsnorm/mix out (GEMM A)
static __device__ __align__(128) float  g_cur [MM*DD];          // pass-1 residual state (= h1)
static __device__ __align__(128) float  g_x2  [MM*DD];          // pass-2 residual state
static __device__ __align__(128) __half g_qa  [BB*HH*SS*KAUG];
static __device__ __align__(128) __half g_ka  [BB*HH*SS*KAUG];
static __device__ __align__(128) __half g_vt  [BB*HH*DHD*SS];   // per-head [DHD, S]
static __device__ __align__(128) float  g_sum [BB*HH*SS];       // softmax row sums (self-zeroing)
static __device__ __align__(128) __half g_ph  [(long long)BB*HH*SS*SS];  // unnorm probs fp16
static __device__ __align__(128) __half g_hr  [MM*FF];          // FFN silu(g)*u (unmixed)
static __device__ __align__(128) __half g_hh  [MM*FF];          // FFN hidden mixed (GEMM A)
// fp16 weights
static __device__ __align__(128) __half g_wqkv[3*DD*DD];
static __device__ __align__(128) __half g_wo  [DD*DD];
static __device__ __align__(128) __half g_wgu [2*FF*DD];        // interleaved (gate_j, up_j) rows
static __device__ __align__(128) __half g_wd  [DD*FF];

// ---------------- helpers ----------------
__device__ __forceinline__ uint32_t smem_u32(const void* p) {
    uint32_t a;
    asm("{ .reg .u64 t; cvta.to.shared.u64 t, %1; cvt.u32.u64 %0, t; }" : "=r"(a) : "l"(p));
    return a;
}
__device__ __forceinline__ void cpasync16(uint32_t dst, const void* src) {
    asm volatile("cp.async.cg.shared.global [%0], [%1], 16;" :: "r"(dst), "l"(src));
}
#define CP_COMMIT()  asm volatile("cp.async.commit_group;" ::: "memory")
#define CP_WAIT1()   asm volatile("cp.async.wait_group 1;" ::: "memory")

__device__ __forceinline__ void ldmx4(uint32_t* r, uint32_t addr) {
    asm volatile("ldmatrix.sync.aligned.m8n8.x4.shared.b16 {%0,%1,%2,%3}, [%4];"
        : "=r"(r[0]), "=r"(r[1]), "=r"(r[2]), "=r"(r[3]) : "r"(addr));
}
__device__ __forceinline__ void mma16816(float* c, const uint32_t* a, uint32_t b0, uint32_t b1) {
    asm volatile("mma.sync.aligned.m16n8k16.row.col.f32.f16.f16.f32 "
        "{%0,%1,%2,%3}, {%4,%5,%6,%7}, {%8,%9}, {%0,%1,%2,%3};"
        : "+f"(c[0]), "+f"(c[1]), "+f"(c[2]), "+f"(c[3])
        : "r"(a[0]), "r"(a[1]), "r"(a[2]), "r"(a[3]), "r"(b0), "r"(b1));
}
__device__ __forceinline__ uint2 f4_to_h4(float4 v) {
    __half2 lo = __floats2half2_rn(v.x, v.y);
    __half2 hi = __floats2half2_rn(v.z, v.w);
    return make_uint2(*(uint32_t*)&lo, *(uint32_t*)&hi);
}

// ---------------- fp16 tensor-core GEMM with fused epilogues ----------------
// C[M,N](TO) = A[M,K](f16) * B[N,K](f16)^T
// ADD (TO=float): C += acc; addsrc: C = addsrc + acc;
//                 addsrc+addsrc2: C = (1+BETA)*addsrc - BETA*addsrc2 + acc.
// CTA tile 128x128, chunk = 64 halves (128B rows), 3 smem slots, single-barrier
// mainloop, 2 CTA/SM.
// TRI: blockIdx.x enumerates lower-triangle 128x128 blocks (causal scores).
// PVK: K limited to (blockIdx.y+1)*128 halves (causal PV).
// MIX: PV epilogue — 1/sum from sums buffer (then self-zero), hadamard-mix along d,
//      transpose-write fp16 xn.
// QKV: RoPE+augment epilogue for q/k heads (C=qa / aux1=ka), v transpose into aux2=vt.
// GLU: interleaved gate/up weights; epilogue writes silu(g)*u fp16 [M,F].
// SMAX: scores epilogue — e = exp(acc*SCALE - ESHIFT) causal-masked, fp16 write,
//       atomicAdd per-row partial sums into sums buffer.
#define HSTAGE 32768    // A:128 rows + B:128 rows, 128B each
#define HSMEM  (3*HSTAGE)
#define STGN   (128*129)   // fp32 staging floats (66048 B)

template<typename TO, bool ADD, bool TRI, bool PVK, bool MIX, bool QKV, bool GLU, bool SMAX>
__global__ void __launch_bounds__(256, 2) hgemm(
    const __half* __restrict__ A, const __half* __restrict__ B, TO* __restrict__ C,
    int Kn, int Nn, long long sA, long long sB, long long sC,
    float* __restrict__ sums, __half* __restrict__ aux1, __half* __restrict__ aux2,
    const float* __restrict__ addsrc, const float* __restrict__ addsrc2)
{
    extern __shared__ __align__(128) char sm[];
    const uint32_t sbase = smem_u32(sm);

    int bi, bj;
    if (TRI) {
        int x = blockIdx.x, i = 0;
        while ((i + 1) * (i + 2) / 2 <= x) i++;
        bi = i; bj = x - i * (i + 1) / 2;
    } else { bi = blockIdx.y; bj = blockIdx.x; }

    A += (long long)blockIdx.z * sA + (long long)(bi * 128) * Kn;
    B += (long long)blockIdx.z * sB + (long long)(bj * 128) * Kn;
    C += (long long)blockIdx.z * sC;

    const int NC = PVK ? 2 * (blockIdx.y + 1) : (Kn >> 6);

    const int tid = threadIdx.x, warp = tid >> 5, lane = tid & 31;
    const int gid = lane >> 2, tig = lane & 3;
    const int wm = (warp & 3) * 32, wn = (warp >> 2) * 64;

    const int mi = lane >> 3, ri = lane & 7;
    const int fro = (mi & 1) * 8 + ri;
    const int khalf = mi >> 1;

    float acc[2][8][4];
#pragma unroll
    for (int mt = 0; mt < 2; mt++)
#pragma unroll
        for (int nt = 0; nt < 8; nt++)
#pragma unroll
            for (int j = 0; j < 4; j++) acc[mt][nt][j] = 0.f;

    const int lr = tid >> 3;
    const int lseg = tid & 7;

    auto load = [&](int chunk) {
        if (chunk < NC) {
            const uint32_t st = sbase + (uint32_t)(chunk % 3) * HSTAGE;
            const __half* Ag = A + chunk * 64;
            const __half* Bg = B + chunk * 64;
#pragma unroll
            for (int it = 0; it < 4; it++) {
                int r = lr + it * 32;
                uint32_t off = (uint32_t)(r * 128 + ((lseg ^ (r & 7)) << 4));
                cpasync16(st + off,         Ag + (long long)r * Kn + lseg * 8);
                cpasync16(st + 16384 + off, Bg + (long long)r * Kn + lseg * 8);
            }
        }
        CP_COMMIT();
    };

    load(0);
    load(1);

    const int arow[2] = { wm + fro, wm + 16 + fro };
    const int brow[4] = { wn + fro, wn + 16 + fro, wn + 32 + fro, wn + 48 + fro };

    for (int c = 0; c < NC; c++) {
        CP_WAIT1();
        __syncthreads();
        load(c + 2);

        const uint32_t st = sbase + (uint32_t)(c % 3) * HSTAGE;
#pragma unroll
        for (int kb = 0; kb < 64; kb += 16) {
            const int ks = (kb >> 3) + khalf;
            uint32_t a[2][4], b[4][4];
#pragma unroll
            for (int mt = 0; mt < 2; mt++) {
                int r = arow[mt];
                ldmx4(a[mt], st + (uint32_t)(r * 128 + ((ks ^ (r & 7)) << 4)));
            }
#pragma unroll
            for (int np = 0; np < 4; np++) {
                int r = brow[np];
                ldmx4(b[np], st + 16384u + (uint32_t)(r * 128 + ((ks ^ (r & 7)) << 4)));
            }
#pragma unroll
            for (int mt = 0; mt < 2; mt++)
#pragma unroll
                for (int nt = 0; nt < 8; nt++)
                    mma16816(acc[mt][nt], a[mt], b[nt >> 1][nt & 1], b[nt >> 1][2 + (nt & 1)]);
        }
    }

    if constexpr (GLU) {
        __half* hr = (__half*)C;          // stride FF
#pragma unroll
        for (int mt = 0; mt < 2; mt++) {
            int row0 = bi * 128 + wm + mt * 16 + gid;
#pragma unroll
            for (int nt = 0; nt < 8; nt++) {
                int jg = bj * 64 + ((wn + nt * 8) >> 1) + tig;
                float g0 = acc[mt][nt][0], u0 = acc[mt][nt][1];
                float g1 = acc[mt][nt][2], u1 = acc[mt][nt][3];
                hr[(long long)row0 * FF + jg]       = __float2half(g0 / (1.f + __expf(-g0)) * u0);
                hr[(long long)(row0 + 8) * FF + jg] = __float2half(g1 / (1.f + __expf(-g1)) * u1);
            }
        }
        return;
    }

    if constexpr (MIX || QKV || SMAX) {
        float* stg = (float*)sm;
        __syncthreads();
#pragma unroll
        for (int mt = 0; mt < 2; mt++) {
            int rr = wm + mt * 16 + gid;
#pragma unroll
            for (int nt = 0; nt < 8; nt++) {
                int cc = wn + nt * 8 + 2 * tig;
                stg[rr * 129 + cc]           = acc[mt][nt][0];
                stg[rr * 129 + cc + 1]       = acc[mt][nt][1];
                stg[(rr + 8) * 129 + cc]     = acc[mt][nt][2];
                stg[(rr + 8) * 129 + cc + 1] = acc[mt][nt][3];
            }
        }
        __syncthreads();
    }

    if constexpr (SMAX) {
        float* stg = (float*)sm;
        float* sred = (float*)(sm + STGN * 4);    // 256 floats after staging
        const int bh = blockIdx.z;
        const int r = tid >> 1, c0 = (tid & 1) * 64;
        const int qi = bi * 128 + r;
        __half* dst = (__half*)C + (long long)qi * SS + bj * 128 + c0;
        float sum = 0.f;
#pragma unroll
        for (int k = 0; k < 64; k += 8) {
            __half ev[8];
#pragma unroll
            for (int u = 0; u < 8; u++) {
                int kj = bj * 128 + c0 + k + u;
                float e = (kj <= qi) ? __expf(stg[r * 129 + c0 + k + u] * SCALE - ESHIFT) : 0.f;
                ev[u] = __float2half(e);
                sum += e;
            }
            *(uint4*)(dst + k) = *(uint4*)ev;
        }
        sred[tid] = sum;
        __syncthreads();
        if (tid < 128)
            atomicAdd(&sums[(long long)bh * SS + bi * 128 + tid],
                      sred[2 * tid] + sred[2 * tid + 1]);
        return;
    }

    if constexpr (MIX) {
        float* stg = (float*)sm;
        float* sinv = (float*)(sm + STGN * 4);    // 128 floats after staging
        const int bh = blockIdx.z;
        const int b = bh >> 4, h = bh & 15;
        // 1/sum per row (replaces recip_k)
        if (tid < 128) sinv[tid] = 1.f / sums[(long long)bh * SS + bi * 128 + tid];
        __syncthreads();
        __half* xo = (__half*)C;          // C = xn base (sC == 0)
        for (int i = tid; i < 128 * 128; i += 256) {
            int r = i >> 7, d = i & 127;
            int sg = bi * 128 + r;
            float iv = sinv[r];
            float v  = stg[r * 129 + d] * iv;
            float pv = stg[r * 129 + ((d + 127) & 127)] * iv;
            xo[((long long)(b * SS + sg)) * DD + h * DHD + d] =
                __float2half(v * (1.f + HS * pv));
        }
        __syncthreads();                  // all reads of sums done
        // self-zero for the next SMAX accumulation (replaces zero_k)
        if (tid < 128) sums[(long long)bh * SS + bi * 128 + tid] = 0.f;
        return;
    }

    if constexpr (QKV) {
        float* stg = (float*)sm;
        const int htype = bj >> 4, h = bj & 15;
        const int bq = (bi * 128) >> 10;
        const int s0 = (bi * 128) & 1023;
        if (htype < 2) {
            __half* dst = (htype == 0) ? (__half*)C : aux1;   // qa : ka
            for (int i = tid; i < 128 * 64; i += 256) {
                int r = i >> 6, dd = i & 63;
                int s = s0 + r;
                float v1 = stg[r * 129 + dd];
                float v2 = stg[r * 129 + dd + 64];
                float invf = __expf(-(float)dd * (9.210340371976184f / 64.0f));
                float ang = (float)s * invf;
                float cs, sn; __sincosf(ang, &sn, &cs);
                float o1 = v1 * cs - v2 * sn;
                float o2 = v1 * sn + v2 * cs;
                long long base = (((long long)(bq * HH + h)) * SS + s) * KAUG;
                dst[base + dd]              = __float2half(o1);
                dst[base + HALF + dd]       = __float2half(o2);
                dst[base + DHD + dd]        = __float2half(SQLAM * o1 * o1);
                dst[base + DHD + HALF + dd] = __float2half(SQLAM * o2 * o2);
            }
        } else {
            const int bh = bq * HH + h;
            for (int i = tid; i < 128 * 128; i += 256) {
                int d = i >> 7, sl = i & 127;
                aux2[((long long)(bh * DHD + d)) * SS + s0 + sl] =
                    __float2half(stg[sl * 129 + d]);
            }
        }
        return;
    }

    // standard epilogue
#pragma unroll
    for (int mt = 0; mt < 2; mt++) {
        int r0 = bi * 128 + wm + mt * 16 + gid;
#pragma unroll
        for (int nt = 0; nt < 8; nt++) {
            int cc = bj * 128 + wn + nt * 8 + 2 * tig;
            TO* p0 = C + (long long)r0 * Nn + cc;
            TO* p1 = p0 + 8 * (long long)Nn;
            if constexpr (sizeof(TO) == 2) {
                *(__half2*)p0 = __floats2half2_rn(acc[mt][nt][0], acc[mt][nt][1]);
                *(__half2*)p1 = __floats2half2_rn(acc[mt][nt][2], acc[mt][nt][3]);
            } else if (ADD) {
                if (addsrc2) {
                    const float* s0p = addsrc  + (long long)r0 * Nn + cc;
                    const float* s1p = s0p + 8 * (long long)Nn;
                    const float* t0p = addsrc2 + (long long)r0 * Nn + cc;
                    const float* t1p = t0p + 8 * (long long)Nn;
                    p0[0] = (1.f + BETA) * s0p[0] - BETA * t0p[0] + acc[mt][nt][0];
                    p0[1] = (1.f + BETA) * s0p[1] - BETA * t0p[1] + acc[mt][nt][1];
                    p1[0] = (1.f + BETA) * s1p[0] - BETA * t1p[0] + acc[mt][nt][2];
                    p1[1] = (1.f + BETA) * s1p[1] - BETA * t1p[1] + acc[mt][nt][3];
                } else if (addsrc) {
                    const float* s0p = addsrc + (long long)r0 * Nn + cc;
                    const float* s1p = s0p + 8 * (long long)Nn;
                    p0[0] = s0p[0] + acc[mt][nt][0]; p0[1] = s0p[1] + acc[mt][nt][1];
                    p1[0] = s1p[0] + acc[mt][nt][2]; p1[1] = s1p[1] + acc[mt][nt][3];
                } else {
                    p0[0] += acc[mt][nt][0]; p0[1] += acc[mt][nt][1];
                    p1[0] += acc[mt][nt][2]; p1[1] += acc[mt][nt][3];
                }
            } else {
                p0[0] = acc[mt][nt][0]; p0[1] = acc[mt][nt][1];
                p1[0] = acc[mt][nt][2]; p1[1] = acc[mt][nt][3];
            }
        }
    }
}

// ---------------- RMSNorm -> fp16 (float4 loads, uint2 fp16 stores) ----------------
// X2MODE: input value = (1+beta)*x[i] - beta*x2src[i] (fused x2 computation)
template<bool X2MODE>
__global__ void rmsnorm_k(const float* __restrict__ x, const float* __restrict__ x2src,
                          const float* __restrict__ sc, __half* __restrict__ o)
{
    const int row = blockIdx.x;
    const float4* xr = (const float4*)(x + (long long)row * DD);
    const float4* sc4 = (const float4*)sc;
    uint2* orw = (uint2*)(o + (long long)row * DD);
    const int tid = threadIdx.x;

    float4 v0 = xr[tid], v1 = xr[tid + 256];
    if (X2MODE) {
        const float4* yr = (const float4*)(x2src + (long long)row * DD);
        float4 y0 = yr[tid], y1 = yr[tid + 256];
        v0 = make_float4((1.f+BETA)*v0.x - BETA*y0.x, (1.f+BETA)*v0.y - BETA*y0.y,
                         (1.f+BETA)*v0.z - BETA*y0.z, (1.f+BETA)*v0.w - BETA*y0.w);
        v1 = make_float4((1.f+BETA)*v1.x - BETA*y1.x, (1.f+BETA)*v1.y - BETA*y1.y,
                         (1.f+BETA)*v1.z - BETA*y1.z, (1.f+BETA)*v1.w - BETA*y1.w);
    }
    float s = v0.x*v0.x + v0.y*v0.y + v0.z*v0.z + v0.w*v0.w
            + v1.x*v1.x + v1.y*v1.y + v1.z*v1.z + v1.w*v1.w;
    __shared__ float red[256];
    red[tid] = s; __syncthreads();
    for (int t = 128; t > 0; t >>= 1) {
        if (tid < t) red[tid] += red[tid + t];
        __syncthreads();
    }
    float r = rsqrtf(red[0] * (1.0f / DD) + EPSV);
    float4 s0 = sc4[tid], s1 = sc4[tid + 256];
    float4 o0 = make_float4(v0.x*r*s0.x, v0.y*r*s0.y, v0.z*r*s0.z, v0.w*r*s0.w);
    float4 o1 = make_float4(v1.x*r*s1.x, v1.y*r*s1.y, v1.z*r*s1.z, v1.w*r*s1.w);
    orw[tid]       = f4_to_h4(o0);
    orw[tid + 256] = f4_to_h4(o1);
}

// ---------------- FFN hadamard mix (vectorized): hh[c] = hr[c]*(1+HS*hr[c-1]) ----------------
__global__ void mixf_k(const __half* __restrict__ hr, __half* __restrict__ hh)
{
    int t = blockIdx.x * 256 + threadIdx.x;       // M*F/8 threads
    int m = t >> 10;
    int c0 = (t & 1023) << 3;
    const __half* row = hr + (long long)m * FF;
    __half in[8];
    *(uint4*)in = *(const uint4*)(row + c0);
    float hprev = __half2float(row[(c0 + FF - 1) & (FF - 1)]);
    __half outv[8];
#pragma unroll
    for (int k = 0; k < 8; k++) {
        float h = __half2float(in[k]);
        outv[k] = __float2half(h * (1.f + HS * hprev));
        hprev = h;
    }
    *(uint4*)(hh + (long long)m * FF + c0) = *(uint4*)outv;
}

// ---------------- unified weight conversion (all 7 fp32 matrices -> fp16) ----------------
#define NQ4 (DD*DD/4)
#define NW4 (FF*DD/4)
#define WCONV_TOTAL (4*NQ4 + 3*NW4)

__global__ void __launch_bounds__(256) wconv_k(
    const float4* __restrict__ wq, const float4* __restrict__ wk,
    const float4* __restrict__ wv, const float4* __restrict__ wo,
    const float4* __restrict__ wg, const float4* __restrict__ wu,
    const float4* __restrict__ wdd,
    uint2* __restrict__ dqkv, uint2* __restrict__ dwo,
    uint2* __restrict__ dgu,  uint2* __restrict__ dwd)
{
    const int G = gridDim.x * 256;
    int i = blockIdx.x * 256 + threadIdx.x;
#pragma unroll
    for (int it = 0; it < 4; it++, i += G) {
        if (i < 4 * NQ4) {
            int seg = i >> 20, off = i & (NQ4 - 1);
            const float4* s = (seg == 0) ? wq : (seg == 1) ? wk : (seg == 2) ? wv : wo;
            uint2 h = f4_to_h4(__ldcs(s + off));
            if (seg < 3) dqkv[(long long)seg * NQ4 + off] = h;
            else         dwo[off] = h;
        } else if (i < 4 * NQ4 + NW4) {
            int off = i - 4 * NQ4;
            dwd[off] = f4_to_h4(__ldcs(wdd + off));
        } else {
            int e = i - 4 * NQ4 - NW4;          // 0 .. 2*NW4
            int isU = e >= NW4;
            int off = isU ? e - NW4 : e;
            const float4* s = isU ? wu : wg;
            int j = off >> 9, c = off & 511;    // DD/4 = 512 float4 per row
            dgu[((long long)(2 * j + isU) << 9) + c] = f4_to_h4(__ldcs(s + off));
        }
    }
}

__global__ void final_k(float* __restrict__ out, const float* __restrict__ h1,
                        const float* __restrict__ h2, int n4)
{
    int i = blockIdx.x * 256 + threadIdx.x;
    if (i < n4) {
        float4 a = ((const float4*)h1)[i];
        float4 b = ((const float4*)h2)[i];
        float4 r;
        r.x = fminf(fmaxf(ALPHA * a.x + (1.f - ALPHA) * b.x, -CLIPV), CLIPV);
        r.y = fminf(fmaxf(ALPHA * a.y + (1.f - ALPHA) * b.y, -CLIPV), CLIPV);
        r.z = fminf(fmaxf(ALPHA * a.z + (1.f - ALPHA) * b.z, -CLIPV), CLIPV);
        r.w = fminf(fmaxf(ALPHA * a.w + (1.f - ALPHA) * b.w, -CLIPV), CLIPV);
        ((float4*)out)[i] = r;
    }
}

// ---------------- host orchestration ----------------
// nsrc/nsrc2: inputs to first rmsnorm. Pass 1: (x, null). Pass 2: (h1, x) fused x2.
// addsrc/addsrc2: Wo epilogue residual sources (same pattern).
static void run_pass(const __half* wqkv, const __half* wo, const __half* wgu, const __half* wd,
                     const float* na, const float* nb,
                     const float* nsrc, const float* nsrc2,
                     const float* addsrc, const float* addsrc2,
                     float* cur, __half* xn,
                     __half* qa, __half* ka, __half* vt, float* sums,
                     __half* ph, __half* hr, __half* hh)
{
    const int nMF = MM * FF;

    if (nsrc2) rmsnorm_k<true><<<MM, 256>>>(nsrc, nsrc2, na, xn);
    else       rmsnorm_k<false><<<MM, 256>>>(nsrc, nullptr, na, xn);

    // fused QKV + RoPE/augment + V-transpose: writes qa, ka, vt directly
    hgemm<__half,false,false,false,false,true,false,false><<<dim3(48, MM/128, 1), 256, HSMEM>>>(
        xn, wqkv, qa, DD, 3*DD, 0, 0, 0, nullptr, ka, vt, nullptr, nullptr);

    // causal scores + fused shifted-exp softmax epilogue -> ph + row sums (pre-zeroed)
    hgemm<__half,false,true,false,false,false,false,true><<<dim3(36, 1, BB*HH), 256, HSMEM>>>(
        qa, ka, ph, KAUG, SS,
        (long long)SS*KAUG, (long long)SS*KAUG, (long long)SS*SS, sums, nullptr, nullptr, nullptr, nullptr);

    // PV with causal K truncation + fused 1/sum + mix/transpose epilogue -> xn
    // (also self-zeroes sums for the next pass/replay)
    hgemm<__half,false,false,true,true,false,false,false><<<dim3(1, SS/128, BB*HH), 256, HSMEM>>>(
        ph, vt, xn, SS, DHD,
        (long long)SS*SS, (long long)SS*DHD, 0, sums, nullptr, nullptr, nullptr, nullptr);

    hgemm<float,true,false,false,false,false,false,false><<<dim3(DD/128, MM/128, 1), 256, HSMEM>>>(
        xn, wo, cur, DD, DD, 0, 0, 0, nullptr, nullptr, nullptr, addsrc, addsrc2);

    rmsnorm_k<false><<<MM, 256>>>(cur, nullptr, nb, xn);
    // fused gate|up (interleaved weights) + silu*up epilogue -> hr [M,F]
    hgemm<__half,false,false,false,false,false,true,false><<<dim3(2*FF/128, MM/128, 1), 256, HSMEM>>>(
        xn, wgu, hr, DD, 2*FF, 0, 0, 0, nullptr, nullptr, nullptr, nullptr, nullptr);
    mixf_k<<<nMF/8/256, 256>>>(hr, hh);
    hgemm<float,true,false,false,false,false,false,false><<<dim3(DD/128, MM/128, 1), 256, HSMEM>>>(
        hh, wd, cur, FF, DD, 0, 0, 0, nullptr, nullptr, nullptr, nullptr, nullptr);
}

extern "C" void kernel_launch(void* const* d_in, const int* in_sizes, int n_in,
                              void* d_out, int out_size)
{
    (void)in_sizes; (void)n_in; (void)out_size;
    const float* x   = (const float*)d_in[0];
    const float* Wq0 = (const float*)d_in[1];
    const float* Wk0 = (const float*)d_in[2];
    const float* Wv0 = (const float*)d_in[3];
    const float* Wo0 = (const float*)d_in[4];
    // d_in[5] = gate_w: unused (rotate_half invariance => o2 == o1)
    const float* n1 = (const float*)d_in[6];
    const float* n2 = (const float*)d_in[7];
    const float* n3 = (const float*)d_in[8];
    const float* n4 = (const float*)d_in[9];
    const float* Wg0 = (const float*)d_in[10];
    const float* Wu0 = (const float*)d_in[11];
    const float* Wd0 = (const float*)d_in[12];
    float* out = (float*)d_out;

    cudaFuncSetAttribute(hgemm<__half,false,false,false,false,true,false,false>, cudaFuncAttributeMaxDynamicSharedMemorySize, HSMEM);
    cudaFuncSetAttribute(hgemm<float,true,false,false,false,false,false,false>,  cudaFuncAttributeMaxDynamicSharedMemorySize, HSMEM);
    cudaFuncSetAttribute(hgemm<__half,false,true,false,false,false,false,true>,  cudaFuncAttributeMaxDynamicSharedMemorySize, HSMEM);
    cudaFuncSetAttribute(hgemm<__half,false,false,true,true,false,false,false>,  cudaFuncAttributeMaxDynamicSharedMemorySize, HSMEM);
    cudaFuncSetAttribute(hgemm<__half,false,false,false,false,false,true,false>, cudaFuncAttributeMaxDynamicSharedMemorySize, HSMEM);

    __half *xn, *qa, *ka, *vt, *ph, *hr, *hh, *wqkv, *wo, *wgu, *wd;
    float *cur, *x2, *sums;
    cudaGetSymbolAddress((void**)&xn,  g_xn);
    cudaGetSymbolAddress((void**)&cur, g_cur);
    cudaGetSymbolAddress((void**)&x2,  g_x2);
    cudaGetSymbolAddress((void**)&qa,  g_qa);
    cudaGetSymbolAddress((void**)&ka,  g_ka);
    cudaGetSymbolAddress((void**)&vt,  g_vt);
    cudaGetSymbolAddress((void**)&sums,g_sum);
    cudaGetSymbolAddress((void**)&ph,  g_ph);
    cudaGetSymbolAddress((void**)&hr,  g_hr);
    cudaGetSymbolAddress((void**)&hh,  g_hh);
    cudaGetSymbolAddress((void**)&wqkv,g_wqkv);
    cudaGetSymbolAddress((void**)&wo,  g_wo);
    cudaGetSymbolAddress((void**)&wgu, g_wgu);
    cudaGetSymbolAddress((void**)&wd,  g_wd);

    const int nMD = MM * DD;

    // unified weight conversion: one kernel, 16M float4 units, 4/thread
    wconv_k<<<WCONV_TOTAL/1024, 256>>>(
        (const float4*)Wq0, (const float4*)Wk0, (const float4*)Wv0, (const float4*)Wo0,
        (const float4*)Wg0, (const float4*)Wu0, (const float4*)Wd0,
        (uint2*)wqkv, (uint2*)wo, (uint2*)wgu, (uint2*)wd);

    // pass 1: rmsnorm reads x; Wo epilogue initializes cur = x + attn
    // (g_sum starts zero: static init on first call, MIX self-zero thereafter)
    run_pass(wqkv, wo, wgu, wd, n1, n2, x, nullptr, x, nullptr,
             cur, xn, qa, ka, vt, sums, ph, hr, hh);

    // pass 2: first rmsnorm computes x2 = (1+b)h1 - b*x inline; Wo epilogue
    // writes x2buf = (1+b)h1 - b*x + attn (x2_k eliminated)
    run_pass(wqkv, wo, wgu, wd, n3, n4, cur, x, cur, x,
             x2, xn, qa, ka, vt, sums, ph, hr, hh);

    // out = clip(alpha*h1 + (1-alpha)*h2)
    final_k<<<(nMD/4+255)/256, 256>>>(out, cur, x2, nMD/4);
}